// round 3
// baseline (speedup 1.0000x reference)
#include <cuda_runtime.h>
#include <math.h>

#define Bk 1024
#define Tk 200
#define Hk 128
#define BT (1024*200)

#define PJ 132          // proj smem stride
#define WS_STRIDE 132
#define LN_STRIDE 130

// Scratch (static device globals: allocation-free at launch time)
__device__ float g_x[3ull * BT * Hk];   // xu, xr, xg projections  [3][B*T][128]
__device__ float g_s[BT];               // attention scores
__device__ float g_att[BT];             // softmax(att) over T

typedef unsigned long long u64;

__device__ __forceinline__ float sigmoidf_(float x) {
    return 1.0f / (1.0f + expf(-x));
}

// ---- packed f32x2 helpers (SASS FFMA2 path, PTX-only) ----
__device__ __forceinline__ u64 ffma2(u64 a, u64 b, u64 c) {
    u64 d;
    asm("fma.rn.f32x2 %0, %1, %2, %3;" : "=l"(d) : "l"(a), "l"(b), "l"(c));
    return d;
}
__device__ __forceinline__ u64 fadd2(u64 a, u64 b) {
    u64 d;
    asm("add.rn.f32x2 %0, %1, %2;" : "=l"(d) : "l"(a), "l"(b));
    return d;
}
__device__ __forceinline__ u64 dup2(float x) {
    u64 d;
    asm("mov.b64 %0, {%1, %1};" : "=l"(d) : "f"(x));
    return d;
}
__device__ __forceinline__ float2 unpack2(u64 v) {
    float2 r;
    asm("mov.b64 {%0, %1}, %2;" : "=f"(r.x), "=f"(r.y) : "l"(v));
    return r;
}

// ---------------------------------------------------------------------------
// Kernel A: projection GEMMs, one weight per blockIdx.y.
//   y=0: attention score s[b,t] = dot(targets@W_w^T + W_b, history)
//   y=1..3: g_x[y-1] = history @ {xu,xr,xg}_w^T + bias
// 512 threads, 4x8 register micro-tile, FFMA2 inner loop.
// ---------------------------------------------------------------------------
__global__ void proj_kernel(const float* __restrict__ targets,
                            const float* __restrict__ history,
                            const float* __restrict__ Ww,  const float* __restrict__ Wb,
                            const float* __restrict__ xuw, const float* __restrict__ xub,
                            const float* __restrict__ xrw, const float* __restrict__ xrb,
                            const float* __restrict__ xgw, const float* __restrict__ xgb)
{
    extern __shared__ float sm[];
    float* Hs  = sm;                 // [128 col/k][PJ row] history, transposed
    float* Ws  = Hs + 128 * PJ;      // [128 k][PJ o]       weight, transposed
    float* Ts  = Ws + 128 * PJ;      // [128 k][PJ row]     targets, transposed (y=0 only)
    float* bsm = Ts + 128 * PJ;      // [128] bias
    float* red = bsm + 128;          // [128 row][16] score reduction (y=0 only)

    const int tid = threadIdx.x;
    const int bt0 = blockIdx.x * 128;
    const int w   = blockIdx.y;

    const float* wsrc = (w == 0) ? Ww  : (w == 1) ? xuw : (w == 2) ? xrw : xgw;
    const float* bsrc = (w == 0) ? Wb  : (w == 1) ? xub : (w == 2) ? xrb : xgb;

    // Stage tiles (transposed: [k][row] / [k][o])
    for (int idx = tid; idx < 128 * 128; idx += 512) {
        int row = idx >> 7, k = idx & 127;
        Hs[k * PJ + row] = history[(size_t)(bt0 + row) * 128 + k];
        Ws[k * PJ + row] = wsrc[(size_t)row * 128 + k];   // row == o here
    }
    if (w == 0) {
        for (int idx = tid; idx < 128 * 128; idx += 512) {
            int row = idx >> 7, k = idx & 127;
            Ts[k * PJ + row] = targets[(size_t)(bt0 + row) * 128 + k];
        }
    }
    if (tid < 128) bsm[tid] = bsrc[tid];
    __syncthreads();

    const int tx = tid & 15, ty = tid >> 4;     // 16 x 32
    const int r0 = ty * 4, c0 = tx * 8;

    const float* A = (w == 0) ? Ts : Hs;

    u64 acc[4][4];
    #pragma unroll
    for (int i = 0; i < 4; i++)
        #pragma unroll
        for (int j = 0; j < 4; j++) acc[i][j] = 0ull;

    #pragma unroll 4
    for (int k = 0; k < 128; k++) {
        const float* Ak = A + k * PJ;
        const float* Wk = Ws + k * PJ;
        float4 a4 = *(const float4*)(Ak + r0);
        ulonglong2 w01 = *(const ulonglong2*)(Wk + c0);       // cols c0..c0+3
        ulonglong2 w23 = *(const ulonglong2*)(Wk + c0 + 4);   // cols c0+4..c0+7
        u64 ad0 = dup2(a4.x), ad1 = dup2(a4.y), ad2 = dup2(a4.z), ad3 = dup2(a4.w);
        acc[0][0] = ffma2(ad0, w01.x, acc[0][0]);
        acc[0][1] = ffma2(ad0, w01.y, acc[0][1]);
        acc[0][2] = ffma2(ad0, w23.x, acc[0][2]);
        acc[0][3] = ffma2(ad0, w23.y, acc[0][3]);
        acc[1][0] = ffma2(ad1, w01.x, acc[1][0]);
        acc[1][1] = ffma2(ad1, w01.y, acc[1][1]);
        acc[1][2] = ffma2(ad1, w23.x, acc[1][2]);
        acc[1][3] = ffma2(ad1, w23.y, acc[1][3]);
        acc[2][0] = ffma2(ad2, w01.x, acc[2][0]);
        acc[2][1] = ffma2(ad2, w01.y, acc[2][1]);
        acc[2][2] = ffma2(ad2, w23.x, acc[2][2]);
        acc[2][3] = ffma2(ad2, w23.y, acc[2][3]);
        acc[3][0] = ffma2(ad3, w01.x, acc[3][0]);
        acc[3][1] = ffma2(ad3, w01.y, acc[3][1]);
        acc[3][2] = ffma2(ad3, w23.x, acc[3][2]);
        acc[3][3] = ffma2(ad3, w23.y, acc[3][3]);
    }

    if (w == 0) {
        // score: per-row dot of (aw + bias) with history row
        #pragma unroll
        for (int i = 0; i < 4; i++) {
            float p = 0.0f;
            #pragma unroll
            for (int jj = 0; jj < 4; jj++) {
                float2 v = unpack2(acc[i][jj]);
                int c = c0 + jj * 2;
                p += (v.x + bsm[c])     * Hs[c * PJ + (r0 + i)];
                p += (v.y + bsm[c + 1]) * Hs[(c + 1) * PJ + (r0 + i)];
            }
            red[(r0 + i) * 16 + tx] = p;
        }
        __syncthreads();
        if (tid < 128) {
            float s = 0.0f;
            #pragma unroll
            for (int x = 0; x < 16; x++) s += red[tid * 16 + x];
            g_s[(size_t)bt0 + tid] = s;
        }
    } else {
        float* dst = g_x + (size_t)(w - 1) * BT * 128 + (size_t)bt0 * 128;
        ulonglong2 b01 = *(const ulonglong2*)(bsm + c0);
        ulonglong2 b23 = *(const ulonglong2*)(bsm + c0 + 4);
        #pragma unroll
        for (int i = 0; i < 4; i++) {
            ulonglong2 o0, o1;
            o0.x = fadd2(acc[i][0], b01.x);
            o0.y = fadd2(acc[i][1], b01.y);
            o1.x = fadd2(acc[i][2], b23.x);
            o1.y = fadd2(acc[i][3], b23.y);
            *(ulonglong2*)&dst[(size_t)(r0 + i) * 128 + c0]     = o0;
            *(ulonglong2*)&dst[(size_t)(r0 + i) * 128 + c0 + 4] = o1;
        }
    }
}

// ---------------------------------------------------------------------------
// Kernel B: softmax over T per batch row.
// ---------------------------------------------------------------------------
__global__ void softmax_kernel()
{
    __shared__ float red[256];
    const int b = blockIdx.x;
    const int tid = threadIdx.x;

    float v = (tid < Tk) ? g_s[(size_t)b * Tk + tid] : -1e30f;
    red[tid] = v;
    __syncthreads();
    for (int s = 128; s > 0; s >>= 1) {
        if (tid < s) red[tid] = fmaxf(red[tid], red[tid + s]);
        __syncthreads();
    }
    const float mx = red[0];
    __syncthreads();
    float e = (tid < Tk) ? expf(v - mx) : 0.0f;
    red[tid] = e;
    __syncthreads();
    for (int s = 128; s > 0; s >>= 1) {
        if (tid < s) red[tid] += red[tid + s];
        __syncthreads();
    }
    const float inv = 1.0f / red[0];
    if (tid < Tk) g_att[(size_t)b * Tk + tid] = e * inv;
}

// ---------------------------------------------------------------------------
// Kernel C: persistent GRU-style scan + final linear.
// 128 blocks x 8 batch rows, 384 threads. Thread tid -> (gate m = tid/128,
// output col oc = tid%128). FFMA2 matvec, 2 syncthreads per step.
// ---------------------------------------------------------------------------
__global__ void scan_kernel(const float* __restrict__ targets,
                            const float* __restrict__ huw, const float* __restrict__ hub,
                            const float* __restrict__ hrw, const float* __restrict__ hrb,
                            const float* __restrict__ hgw, const float* __restrict__ hgb,
                            const float* __restrict__ ln2w, const float* __restrict__ ln2b,
                            float* __restrict__ out)
{
    extern __shared__ float sm[];
    float* W_s = sm;                          // [3][128 o][WS_STRIDE k]
    float* bsm = W_s + 3 * 128 * WS_STRIDE;   // [3][128]
    float* h_s = bsm + 3 * 128;               // [8][128]
    float* r_s = h_s + 8 * 128;               // [8][128] reset gate / targets stage
    float* u_s = r_s + 8 * 128;               // [8][128] scaled update gate

    const int tid = threadIdx.x;
    const int b0 = blockIdx.x * 8;

    {
        const float* hw[3] = {huw, hrw, hgw};
        const float* hb[3] = {hub, hrb, hgb};
        for (int mm = 0; mm < 3; mm++) {
            for (int idx = tid; idx < 128 * 128; idx += 384) {
                int o = idx >> 7, k = idx & 127;
                W_s[(mm * 128 + o) * WS_STRIDE + k] = hw[mm][idx];
            }
            if (tid < 128) bsm[mm * 128 + tid] = hb[mm][tid];
        }
    }
    for (int idx = tid; idx < 8 * 128; idx += 384) h_s[idx] = 0.0f;
    __syncthreads();

    const int m  = tid >> 7;     // 0: update u, 1: reset r, 2: candidate g + h update
    const int oc = tid & 127;
    const float* wrow = &W_s[(m * 128 + oc) * WS_STRIDE];
    const float  bias = bsm[m * 128 + oc];
    const float* xbase = g_x + (size_t)m * BT * 128 + oc;

    for (int t = 0; t < Tk; t++) {
        // issue global loads early (latency hidden behind matvec)
        float xv[8], attv[8];
        #pragma unroll
        for (int i = 0; i < 8; i++)
            xv[i] = xbase[(size_t)((b0 + i) * Tk + t) * 128];
        if (m == 0) {
            #pragma unroll
            for (int i = 0; i < 8; i++) attv[i] = g_att[(size_t)(b0 + i) * Tk + t];
        }

        u64 aA[8], aB[8];
        #pragma unroll
        for (int i = 0; i < 8; i++) { aA[i] = 0ull; aB[i] = 0ull; }

        #pragma unroll 4
        for (int k = 0; k < 128; k += 4) {
            ulonglong2 w2 = *(const ulonglong2*)&wrow[k];
            #pragma unroll
            for (int i = 0; i < 8; i++) {
                ulonglong2 h2 = *(const ulonglong2*)&h_s[i * 128 + k];
                aA[i] = ffma2(w2.x, h2.x, aA[i]);
                aB[i] = ffma2(w2.y, h2.y, aB[i]);
            }
        }
        float acc[8];
        #pragma unroll
        for (int i = 0; i < 8; i++) {
            float2 s2 = unpack2(fadd2(aA[i], aB[i]));
            acc[i] = s2.x + s2.y;
        }

        if (m == 0) {
            #pragma unroll
            for (int i = 0; i < 8; i++)
                u_s[i * 128 + oc] = sigmoidf_(acc[i] + bias + xv[i]) * attv[i];
        } else if (m == 1) {
            #pragma unroll
            for (int i = 0; i < 8; i++)
                r_s[i * 128 + oc] = sigmoidf_(acc[i] + bias + xv[i]);
        }
        __syncthreads();                 // u_s, r_s ready; matvec reads of h done

        if (m == 2) {
            #pragma unroll
            for (int i = 0; i < 8; i++) {
                float z = acc[i] + bias;                    // h@hg^T + hg_b
                float g = tanhf(xv[i] + r_s[i * 128 + oc] * z);
                float h = h_s[i * 128 + oc];
                h_s[i * 128 + oc] = h + u_s[i * 128 + oc] * (g - h);
            }
        }
        __syncthreads();                 // h ready for next step
    }

    // ---- final: out = concat(h, targets[:,0]) @ ln2_w^T + ln2_b ----
    for (int idx = tid; idx < 8 * 128; idx += 384)
        r_s[idx] = targets[(size_t)((b0 + (idx >> 7)) * Tk) * 128 + (idx & 127)];
    float* lw = W_s;   // [256 k][LN_STRIDE] transposed
    for (int idx = tid; idx < 128 * 256; idx += 384) {
        int o = idx >> 8, k2 = idx & 255;             // ln2_w[o][k2]
        lw[k2 * LN_STRIDE + o] = ln2w[idx];
    }
    __syncthreads();

    if (tid < 128) {
        const int o = tid;
        float acc2[8];
        const float b2 = ln2b[o];
        #pragma unroll
        for (int i = 0; i < 8; i++) acc2[i] = b2;
        #pragma unroll 2
        for (int k = 0; k < 128; k++) {
            float wh = lw[k * LN_STRIDE + o];
            float wt = lw[(128 + k) * LN_STRIDE + o];
            #pragma unroll
            for (int i = 0; i < 8; i++)
                acc2[i] += h_s[i * 128 + k] * wh + r_s[i * 128 + k] * wt;
        }
        #pragma unroll
        for (int i = 0; i < 8; i++)
            out[(size_t)(b0 + i) * 128 + o] = acc2[i];
    }
}

// ---------------------------------------------------------------------------
extern "C" void kernel_launch(void* const* d_in, const int* in_sizes, int n_in,
                              void* d_out, int out_size)
{
    const float* targets = (const float*)d_in[0];
    const float* history = (const float*)d_in[1];
    const float* Ww  = (const float*)d_in[2];
    const float* Wb  = (const float*)d_in[3];
    const float* xuw = (const float*)d_in[4];
    const float* xub = (const float*)d_in[5];
    const float* huw = (const float*)d_in[6];
    const float* hub = (const float*)d_in[7];
    const float* xrw = (const float*)d_in[8];
    const float* xrb = (const float*)d_in[9];
    const float* hrw = (const float*)d_in[10];
    const float* hrb = (const float*)d_in[11];
    const float* xgw = (const float*)d_in[12];
    const float* xgb = (const float*)d_in[13];
    const float* hgw = (const float*)d_in[14];
    const float* hgb = (const float*)d_in[15];
    const float* ln2w = (const float*)d_in[16];
    const float* ln2b = (const float*)d_in[17];
    float* out = (float*)d_out;

    const size_t smA = (size_t)(3 * 128 * PJ + 128 + 128 * 16) * sizeof(float);
    const size_t smC = (size_t)(3 * 128 * WS_STRIDE + 3 * 128 + 3 * 8 * 128) * sizeof(float);

    cudaFuncSetAttribute(proj_kernel, cudaFuncAttributeMaxDynamicSharedMemorySize, (int)smA);
    cudaFuncSetAttribute(scan_kernel, cudaFuncAttributeMaxDynamicSharedMemorySize, (int)smC);

    proj_kernel<<<dim3(BT / 128, 4), 512, smA>>>(targets, history, Ww, Wb,
                                                 xuw, xub, xrw, xrb, xgw, xgb);
    softmax_kernel<<<Bk, 256>>>();
    scan_kernel<<<Bk / 8, 384, smC>>>(targets, huw, hub, hrw, hrb, hgw, hgb,
                                      ln2w, ln2b, out);
}

// round 4
// speedup vs baseline: 1.0929x; 1.0929x over previous
#include <cuda_runtime.h>
#include <math.h>

#define Bk 1024
#define Tk 200
#define BT (1024*200)

#define PJ  132   // proj smem row stride (floats)
#define WST 132   // scan weight row stride
#define HST 132   // scan state row stride
#define LNS 130   // final-linear stride

// k-swizzle: k = ks*32 + it*4 + j  ->  phys = it*16 + ks*4 + j
#define HSWZ(k) ((((k) & 28) << 2) + (((k) >> 5) << 2) + ((k) & 3))

__device__ float g_x[3ull * BT * 128];  // xu, xr, xg projections
__device__ float g_s[BT];               // attention scores
__device__ float g_att[BT];             // softmax weights

typedef unsigned long long u64;

__device__ __forceinline__ u64 ffma2(u64 a, u64 b, u64 c) {
    u64 d;
    asm("fma.rn.f32x2 %0, %1, %2, %3;" : "=l"(d) : "l"(a), "l"(b), "l"(c));
    return d;
}
__device__ __forceinline__ float2 unpack2(u64 v) {
    float2 r;
    asm("mov.b64 {%0, %1}, %2;" : "=f"(r.x), "=f"(r.y) : "l"(v));
    return r;
}

// ---------------------------------------------------------------------------
// Kernel A: projection GEMMs, one weight per blockIdx.y. Row-major smem.
// 512 thr: ty=tid/32 -> rows r0=ty*8; tx=lane -> cols {tx,tx+32,tx+64,tx+96}.
// ---------------------------------------------------------------------------
__global__ __launch_bounds__(512)
void proj_kernel(const float* __restrict__ targets,
                 const float* __restrict__ history,
                 const float* __restrict__ Ww,  const float* __restrict__ Wb,
                 const float* __restrict__ xuw, const float* __restrict__ xub,
                 const float* __restrict__ xrw, const float* __restrict__ xrb,
                 const float* __restrict__ xgw, const float* __restrict__ xgb)
{
    extern __shared__ float sm[];
    float* A_s = sm;                 // [128][PJ]
    float* W_s = A_s + 128 * PJ;     // [128][PJ]
    float* H_s = W_s + 128 * PJ;     // [128][PJ] (y=0 only)
    float* red = H_s + 128 * PJ;     // [128][33] (y=0 only)

    const int tid = threadIdx.x;
    const int bt0 = blockIdx.x * 128;
    const int w   = blockIdx.y;

    const float* wsrc = (w == 0) ? Ww : (w == 1) ? xuw : (w == 2) ? xrw : xgw;
    const float* bsrc = (w == 0) ? Wb : (w == 1) ? xub : (w == 2) ? xrb : xgb;
    const float* asrc = (w == 0) ? targets : history;

    for (int idx = tid; idx < 128 * 32; idx += 512) {
        int row = idx >> 5, kq = idx & 31;
        ((float4*)(A_s + row * PJ))[kq] =
            ((const float4*)(asrc + (size_t)(bt0 + row) * 128))[kq];
        ((float4*)(W_s + row * PJ))[kq] =
            ((const float4*)(wsrc + (size_t)row * 128))[kq];
    }
    if (w == 0) {
        for (int idx = tid; idx < 128 * 32; idx += 512) {
            int row = idx >> 5, kq = idx & 31;
            ((float4*)(H_s + row * PJ))[kq] =
                ((const float4*)(history + (size_t)(bt0 + row) * 128))[kq];
        }
    }

    const int tx = tid & 31, ty = tid >> 5;
    const int r0 = ty * 8;

    float bias_r[4];
    #pragma unroll
    for (int j = 0; j < 4; j++) bias_r[j] = bsrc[tx + 32 * j];

    __syncthreads();

    u64 acc[8][4];
    #pragma unroll
    for (int i = 0; i < 8; i++)
        #pragma unroll
        for (int j = 0; j < 4; j++) acc[i][j] = 0ull;

    #pragma unroll 2
    for (int kq = 0; kq < 32; kq++) {
        ulonglong2 a2[8];
        #pragma unroll
        for (int i = 0; i < 8; i++)
            a2[i] = *(const ulonglong2*)&A_s[(r0 + i) * PJ + kq * 4];
        #pragma unroll
        for (int j = 0; j < 4; j++) {
            ulonglong2 w2 = *(const ulonglong2*)&W_s[(tx + 32 * j) * PJ + kq * 4];
            #pragma unroll
            for (int i = 0; i < 8; i++) {
                acc[i][j] = ffma2(a2[i].x, w2.x, acc[i][j]);
                acc[i][j] = ffma2(a2[i].y, w2.y, acc[i][j]);
            }
        }
    }

    float v[8][4];
    #pragma unroll
    for (int i = 0; i < 8; i++)
        #pragma unroll
        for (int j = 0; j < 4; j++) {
            float2 p = unpack2(acc[i][j]);
            v[i][j] = p.x + p.y;
        }

    if (w == 0) {
        #pragma unroll
        for (int i = 0; i < 8; i++) {
            float p = 0.0f;
            #pragma unroll
            for (int j = 0; j < 4; j++)
                p += (v[i][j] + bias_r[j]) * H_s[(r0 + i) * PJ + tx + 32 * j];
            red[(r0 + i) * 33 + tx] = p;
        }
        __syncthreads();
        if (tid < 128) {
            float s = 0.0f;
            #pragma unroll
            for (int x = 0; x < 32; x++) s += red[tid * 33 + x];
            g_s[(size_t)bt0 + tid] = s;
        }
    } else {
        float* dst = g_x + (size_t)(w - 1) * BT * 128 + (size_t)bt0 * 128;
        #pragma unroll
        for (int i = 0; i < 8; i++)
            #pragma unroll
            for (int j = 0; j < 4; j++)
                dst[(size_t)(r0 + i) * 128 + tx + 32 * j] = v[i][j] + bias_r[j];
    }
}

// ---------------------------------------------------------------------------
__global__ void softmax_kernel()
{
    __shared__ float red[256];
    const int b = blockIdx.x;
    const int tid = threadIdx.x;

    float v = (tid < Tk) ? g_s[(size_t)b * Tk + tid] : -1e30f;
    red[tid] = v;
    __syncthreads();
    for (int s = 128; s > 0; s >>= 1) {
        if (tid < s) red[tid] = fmaxf(red[tid], red[tid + s]);
        __syncthreads();
    }
    const float mx = red[0];
    __syncthreads();
    float e = (tid < Tk) ? expf(v - mx) : 0.0f;
    red[tid] = e;
    __syncthreads();
    for (int s = 128; s > 0; s >>= 1) {
        if (tid < s) red[tid] += red[tid + s];
        __syncthreads();
    }
    const float inv = 1.0f / red[0];
    if (tid < Tk) g_att[(size_t)b * Tk + tid] = e * inv;
}

// ---------------------------------------------------------------------------
// Kernel C: persistent scan. 128 CTAs x 8 rows, 384 thr = 12 warps.
// warp wid: gate m=wid/4, cols c0=(wid%4)*32. lane: ks=lane&3 (k-slice of 32),
// cl=lane>>2 -> cols cbase=c0+cl*4. k stored swizzled (HSWZ).
// ---------------------------------------------------------------------------
__global__ __launch_bounds__(384)
void scan_kernel(const float* __restrict__ targets,
                 const float* __restrict__ huw, const float* __restrict__ hub,
                 const float* __restrict__ hrw, const float* __restrict__ hrb,
                 const float* __restrict__ hgw, const float* __restrict__ hgb,
                 const float* __restrict__ ln2w, const float* __restrict__ ln2b,
                 float* __restrict__ out)
{
    extern __shared__ float sm[];
    float* w_s  = sm;                       // [3*128][WST], swizzled k
    float* h_s  = w_s + 3 * 128 * WST;      // [8][HST], swizzled k
    float* u_s  = h_s + 8 * HST;            // plain col layout
    float* r_s  = u_s + 8 * HST;
    float* zg_s = r_s + 8 * HST;
    float* xg_s = zg_s + 8 * HST;

    const int tid = threadIdx.x;
    const int b0 = blockIdx.x * 8;

    {
        const float* hw[3] = {huw, hrw, hgw};
        for (int mm = 0; mm < 3; mm++)
            for (int idx = tid; idx < 128 * 128; idx += 384) {
                int o = idx >> 7, k = idx & 127;
                w_s[(mm * 128 + o) * WST + HSWZ(k)] = hw[mm][idx];
            }
    }
    for (int idx = tid; idx < 8 * HST; idx += 384) h_s[idx] = 0.0f;

    const int wid = tid >> 5, lane = tid & 31;
    const int m = wid >> 2;
    const int c0 = (wid & 3) * 32;
    const int ks = lane & 3, cl = lane >> 2;
    const int cbase = c0 + cl * 4;
    const int ra = ks, rb = ks + 4;

    const float* hb = (m == 0) ? hub : (m == 1) ? hrb : hgb;
    float bias[4];
    #pragma unroll
    for (int j = 0; j < 4; j++) bias[j] = hb[cbase + j];

    const float* wbase = &w_s[(m * 128 + cbase) * WST];
    const float* xrow_a = g_x + (size_t)m * BT * 128 + (size_t)(b0 + ra) * Tk * 128 + cbase;
    const float* xrow_b = g_x + (size_t)m * BT * 128 + (size_t)(b0 + rb) * Tk * 128 + cbase;
    const float* att_a = g_att + (size_t)(b0 + ra) * Tk;
    const float* att_b = g_att + (size_t)(b0 + rb) * Tk;

    __syncthreads();

    for (int t = 0; t < Tk; t++) {
        float4 xa = *(const float4*)(xrow_a + (size_t)t * 128);
        float4 xb = *(const float4*)(xrow_b + (size_t)t * 128);
        float atta = 0.f, attb = 0.f;
        if (m == 0) { atta = att_a[t]; attb = att_b[t]; }

        u64 acc[4][8];
        #pragma unroll
        for (int j = 0; j < 4; j++)
            #pragma unroll
            for (int r = 0; r < 8; r++) acc[j][r] = 0ull;

        #pragma unroll 2
        for (int it = 0; it < 8; it++) {
            const int off = it * 16 + ks * 4;
            ulonglong2 h2[8];
            #pragma unroll
            for (int r = 0; r < 8; r++)
                h2[r] = *(const ulonglong2*)&h_s[r * HST + off];
            #pragma unroll
            for (int j = 0; j < 4; j++) {
                ulonglong2 w2 = *(const ulonglong2*)&wbase[j * WST + off];
                #pragma unroll
                for (int r = 0; r < 8; r++) {
                    acc[j][r] = ffma2(w2.x, h2[r].x, acc[j][r]);
                    acc[j][r] = ffma2(w2.y, h2[r].y, acc[j][r]);
                }
            }
        }

        float s[4][8];
        #pragma unroll
        for (int j = 0; j < 4; j++)
            #pragma unroll
            for (int r = 0; r < 8; r++) {
                float2 p = unpack2(acc[j][r]);
                s[j][r] = p.x + p.y;
                s[j][r] += __shfl_xor_sync(0xFFFFFFFFu, s[j][r], 1);
                s[j][r] += __shfl_xor_sync(0xFFFFFFFFu, s[j][r], 2);
            }

        float xav[4] = {xa.x, xa.y, xa.z, xa.w};
        float xbv[4] = {xb.x, xb.y, xb.z, xb.w};
        if (m == 0) {
            float4 oa, ob;
            float* pa = (float*)&oa; float* pb = (float*)&ob;
            #pragma unroll
            for (int j = 0; j < 4; j++) {
                pa[j] = atta / (1.0f + expf(-(s[j][ra] + bias[j] + xav[j])));
                pb[j] = attb / (1.0f + expf(-(s[j][rb] + bias[j] + xbv[j])));
            }
            *(float4*)&u_s[ra * HST + cbase] = oa;
            *(float4*)&u_s[rb * HST + cbase] = ob;
        } else if (m == 1) {
            float4 oa, ob;
            float* pa = (float*)&oa; float* pb = (float*)&ob;
            #pragma unroll
            for (int j = 0; j < 4; j++) {
                pa[j] = 1.0f / (1.0f + expf(-(s[j][ra] + bias[j] + xav[j])));
                pb[j] = 1.0f / (1.0f + expf(-(s[j][rb] + bias[j] + xbv[j])));
            }
            *(float4*)&r_s[ra * HST + cbase] = oa;
            *(float4*)&r_s[rb * HST + cbase] = ob;
        } else {
            float4 za, zb;
            float* qa = (float*)&za; float* qb = (float*)&zb;
            #pragma unroll
            for (int j = 0; j < 4; j++) {
                qa[j] = s[j][ra] + bias[j];
                qb[j] = s[j][rb] + bias[j];
            }
            *(float4*)&zg_s[ra * HST + cbase] = za;
            *(float4*)&zg_s[rb * HST + cbase] = zb;
            *(float4*)&xg_s[ra * HST + cbase] = xa;
            *(float4*)&xg_s[rb * HST + cbase] = xb;
        }
        __syncthreads();

        // combine: g = tanh(xg + r*zg); h += u*(g - h)   (u already * att)
        for (int idx = tid; idx < 1024; idx += 384) {
            int row = idx >> 7, c = idx & 127;
            int hp = row * HST + HSWZ(c);
            int pp = row * HST + c;
            float g = tanhf(xg_s[pp] + r_s[pp] * zg_s[pp]);
            float h = h_s[hp];
            h_s[hp] = h + u_s[pp] * (g - h);
        }
        __syncthreads();
    }

    // ---- final: out = concat(h, targets[:,0]) @ ln2_w^T + ln2_b ----
    for (int idx = tid; idx < 8 * 128; idx += 384)
        r_s[(idx >> 7) * HST + (idx & 127)] =
            targets[(size_t)((b0 + (idx >> 7)) * Tk) * 128 + (idx & 127)];
    float* lw = w_s;   // [256 k][LNS] transposed
    for (int idx = tid; idx < 128 * 256; idx += 384) {
        int o = idx >> 8, k2 = idx & 255;
        lw[k2 * LNS + o] = ln2w[idx];
    }
    __syncthreads();

    if (tid < 128) {
        const int o = tid;
        float acc2[8];
        const float b2 = ln2b[o];
        #pragma unroll
        for (int i = 0; i < 8; i++) acc2[i] = b2;
        #pragma unroll 2
        for (int k = 0; k < 128; k++) {
            float wh = lw[k * LNS + o];
            float wt = lw[(128 + k) * LNS + o];
            int hk = HSWZ(k);
            #pragma unroll
            for (int i = 0; i < 8; i++)
                acc2[i] += h_s[i * HST + hk] * wh + r_s[i * HST + k] * wt;
        }
        #pragma unroll
        for (int i = 0; i < 8; i++)
            out[(size_t)(b0 + i) * 128 + o] = acc2[i];
    }
}

// ---------------------------------------------------------------------------
extern "C" void kernel_launch(void* const* d_in, const int* in_sizes, int n_in,
                              void* d_out, int out_size)
{
    const float* targets = (const float*)d_in[0];
    const float* history = (const float*)d_in[1];
    const float* Ww  = (const float*)d_in[2];
    const float* Wb  = (const float*)d_in[3];
    const float* xuw = (const float*)d_in[4];
    const float* xub = (const float*)d_in[5];
    const float* huw = (const float*)d_in[6];
    const float* hub = (const float*)d_in[7];
    const float* xrw = (const float*)d_in[8];
    const float* xrb = (const float*)d_in[9];
    const float* hrw = (const float*)d_in[10];
    const float* hrb = (const float*)d_in[11];
    const float* xgw = (const float*)d_in[12];
    const float* xgb = (const float*)d_in[13];
    const float* hgw = (const float*)d_in[14];
    const float* hgb = (const float*)d_in[15];
    const float* ln2w = (const float*)d_in[16];
    const float* ln2b = (const float*)d_in[17];
    float* out = (float*)d_out;

    const size_t smA = (size_t)(3 * 128 * PJ + 128 * 33) * sizeof(float);
    const size_t smC = (size_t)(3 * 128 * WST + 5 * 8 * HST) * sizeof(float);

    cudaFuncSetAttribute(proj_kernel, cudaFuncAttributeMaxDynamicSharedMemorySize, (int)smA);
    cudaFuncSetAttribute(scan_kernel, cudaFuncAttributeMaxDynamicSharedMemorySize, (int)smC);

    proj_kernel<<<dim3(BT / 128, 4), 512, smA>>>(targets, history, Ww, Wb,
                                                 xuw, xub, xrw, xrb, xgw, xgb);
    softmax_kernel<<<Bk, 256>>>();
    scan_kernel<<<Bk / 8, 384, smC>>>(targets, huw, hub, hrw, hrb, hgw, hgb,
                                      ln2w, ln2b, out);
}

// round 5
// speedup vs baseline: 1.3642x; 1.2482x over previous
#include <cuda_runtime.h>
#include <math.h>
#include <stdint.h>

#define Bk 1024
#define Tk 200
#define BT (1024*200)
#define NTILE 1600        // BT/128
#define NSLOT 148

#define PJ  132   // proj smem row stride (floats)
#define WST 132   // scan weight row stride
#define HST 132   // scan state row stride
#define LNS 130   // final-linear stride

// k-swizzle: k = ks*32 + it*4 + j  ->  phys = it*16 + ks*4 + j
#define HSWZ(k) ((((k) & 28) << 2) + (((k) >> 5) << 2) + ((k) & 3))

__device__ float g_x[3ull * BT * 128];  // xu, xr, xg projections
__device__ float g_aw[(size_t)BT * 128]; // targets @ Ww^T + Wb
__device__ float g_att[BT];              // softmax weights

typedef unsigned long long u64;

__device__ __forceinline__ u64 ffma2(u64 a, u64 b, u64 c) {
    u64 d;
    asm("fma.rn.f32x2 %0, %1, %2, %3;" : "=l"(d) : "l"(a), "l"(b), "l"(c));
    return d;
}
__device__ __forceinline__ float2 unpack2(u64 v) {
    float2 r;
    asm("mov.b64 {%0, %1}, %2;" : "=f"(r.x), "=f"(r.y) : "l"(v));
    return r;
}
__device__ __forceinline__ void cp16(uint32_t saddr, const void* gptr) {
    asm volatile("cp.async.cg.shared.global [%0], [%1], 16;" :: "r"(saddr), "l"(gptr));
}
__device__ __forceinline__ void cp_commit() {
    asm volatile("cp.async.commit_group;");
}

// ---------------------------------------------------------------------------
// Kernel A: persistent projection GEMMs. 592 CTAs = 148 slots x 4 weights.
// Each CTA: stage W once, loop over bt-tiles with cp.async double-buffered A.
//   w=0: g_aw = targets @ Ww^T + Wb
//   w=1..3: g_x[w-1] = history @ {xu,xr,xg}_w^T + bias
// ---------------------------------------------------------------------------
__global__ __launch_bounds__(512)
void proj_kernel(const float* __restrict__ targets,
                 const float* __restrict__ history,
                 const float* __restrict__ Ww,  const float* __restrict__ Wb,
                 const float* __restrict__ xuw, const float* __restrict__ xub,
                 const float* __restrict__ xrw, const float* __restrict__ xrb,
                 const float* __restrict__ xgw, const float* __restrict__ xgb)
{
    extern __shared__ float sm[];
    float* W_s = sm;                 // [128][PJ]
    float* A0  = W_s + 128 * PJ;     // [128][PJ]
    float* A1  = A0 + 128 * PJ;      // [128][PJ]

    const int tid  = threadIdx.x;
    const int w    = blockIdx.x & 3;
    const int slot = blockIdx.x >> 2;

    const float* wsrc = (w == 0) ? Ww : (w == 1) ? xuw : (w == 2) ? xrw : xgw;
    const float* bsrc = (w == 0) ? Wb : (w == 1) ? xub : (w == 2) ? xrb : xgb;
    const float* asrc = (w == 0) ? targets : history;
    float* dstbase = (w == 0) ? g_aw : (g_x + (size_t)(w - 1) * BT * 128);

    // stage weight (row-major, conflict-free)
    for (int idx = tid; idx < 128 * 32; idx += 512) {
        int row = idx >> 5, kq = idx & 31;
        ((float4*)(W_s + row * PJ))[kq] = ((const float4*)(wsrc + (size_t)row * 128))[kq];
    }

    const int tx = tid & 31, ty = tid >> 5;
    const int r0 = ty * 8;
    float bias_r[4];
    #pragma unroll
    for (int j = 0; j < 4; j++) bias_r[j] = bsrc[tx + 32 * j];

    const uint32_t sA0 = (uint32_t)__cvta_generic_to_shared(A0);
    const uint32_t sA1 = (uint32_t)__cvta_generic_to_shared(A1);

    // prefetch first tile into A0
    int tile = slot;
    if (tile < NTILE) {
        const float* src = asrc + (size_t)tile * 128 * 128;
        for (int i = tid; i < 4096; i += 512) {
            int row = i >> 5, kq = i & 31;
            cp16(sA0 + (uint32_t)(row * PJ + kq * 4) * 4, src + (size_t)row * 128 + kq * 4);
        }
    }
    cp_commit();

    int p = 0;
    for (; tile < NTILE; tile += NSLOT) {
        int nxt = tile + NSLOT;
        if (nxt < NTILE) {
            const float* src = asrc + (size_t)nxt * 128 * 128;
            uint32_t sdst = p ? sA0 : sA1;
            for (int i = tid; i < 4096; i += 512) {
                int row = i >> 5, kq = i & 31;
                cp16(sdst + (uint32_t)(row * PJ + kq * 4) * 4, src + (size_t)row * 128 + kq * 4);
            }
            cp_commit();
            asm volatile("cp.async.wait_group 1;");
        } else {
            asm volatile("cp.async.wait_group 0;");
        }
        __syncthreads();

        const float* A_s = p ? A1 : A0;

        u64 acc[8][4];
        #pragma unroll
        for (int i = 0; i < 8; i++)
            #pragma unroll
            for (int j = 0; j < 4; j++) acc[i][j] = 0ull;

        #pragma unroll 2
        for (int kq = 0; kq < 32; kq++) {
            ulonglong2 a2[8];
            #pragma unroll
            for (int i = 0; i < 8; i++)
                a2[i] = *(const ulonglong2*)&A_s[(r0 + i) * PJ + kq * 4];
            #pragma unroll
            for (int j = 0; j < 4; j++) {
                ulonglong2 w2 = *(const ulonglong2*)&W_s[(tx + 32 * j) * PJ + kq * 4];
                #pragma unroll
                for (int i = 0; i < 8; i++) {
                    acc[i][j] = ffma2(a2[i].x, w2.x, acc[i][j]);
                    acc[i][j] = ffma2(a2[i].y, w2.y, acc[i][j]);
                }
            }
        }

        float* dst = dstbase + (size_t)tile * 128 * 128;
        #pragma unroll
        for (int i = 0; i < 8; i++)
            #pragma unroll
            for (int j = 0; j < 4; j++) {
                float2 pr = unpack2(acc[i][j]);
                dst[(size_t)(r0 + i) * 128 + tx + 32 * j] = pr.x + pr.y + bias_r[j];
            }

        p ^= 1;
        __syncthreads();   // compute done before next prefetch overwrites buffer
    }
}

// ---------------------------------------------------------------------------
// Kernel B: fused score + softmax. 1 block per batch row b, 256 threads.
//   s[b,t] = dot(g_aw[b,t,:], history[b,t,:]);  att = softmax_t(s)
// ---------------------------------------------------------------------------
__global__ __launch_bounds__(256)
void score_softmax_kernel(const float* __restrict__ history)
{
    __shared__ float s_sm[256];
    __shared__ float red[256];

    const int b = blockIdx.x;
    const int tid = threadIdx.x;
    const int wid = tid >> 5, lane = tid & 31;

    // scores: warp per t, 25 t per warp
    for (int tt = 0; tt < 25; tt++) {
        int t = wid * 25 + tt;
        const float4* ap = (const float4*)(g_aw + (size_t)(b * Tk + t) * 128);
        const float4* hp = (const float4*)(history + (size_t)(b * Tk + t) * 128);
        float4 a4 = ap[lane];
        float4 h4 = hp[lane];
        float d = a4.x * h4.x + a4.y * h4.y + a4.z * h4.z + a4.w * h4.w;
        #pragma unroll
        for (int s = 16; s > 0; s >>= 1)
            d += __shfl_xor_sync(0xFFFFFFFFu, d, s);
        if (lane == 0) s_sm[t] = d;
    }
    __syncthreads();

    float v = (tid < Tk) ? s_sm[tid] : -1e30f;
    red[tid] = v;
    __syncthreads();
    for (int s = 128; s > 0; s >>= 1) {
        if (tid < s) red[tid] = fmaxf(red[tid], red[tid + s]);
        __syncthreads();
    }
    const float mx = red[0];
    __syncthreads();
    float e = (tid < Tk) ? __expf(v - mx) : 0.0f;
    red[tid] = e;
    __syncthreads();
    for (int s = 128; s > 0; s >>= 1) {
        if (tid < s) red[tid] += red[tid + s];
        __syncthreads();
    }
    const float inv = 1.0f / red[0];
    if (tid < Tk) g_att[(size_t)b * Tk + tid] = e * inv;
}

// ---------------------------------------------------------------------------
// Kernel C: persistent scan. 128 CTAs x 8 rows, 384 thr = 12 warps.
// warp wid: gate m=wid/4, cols c0=(wid%4)*32. lane: ks=lane&3 (k-slice of 32),
// cl=lane>>2 -> cols cbase=c0+cl*4. ALL state arrays stored in HSWZ layout so
// the combine pass iterates physical indices (conflict-free, no address math).
// x/att loads software-pipelined one step ahead.
// ---------------------------------------------------------------------------
__global__ __launch_bounds__(384)
void scan_kernel(const float* __restrict__ targets,
                 const float* __restrict__ huw, const float* __restrict__ hub,
                 const float* __restrict__ hrw, const float* __restrict__ hrb,
                 const float* __restrict__ hgw, const float* __restrict__ hgb,
                 const float* __restrict__ ln2w, const float* __restrict__ ln2b,
                 float* __restrict__ out)
{
    extern __shared__ float sm[];
    float* w_s  = sm;                       // [3*128][WST], swizzled k
    float* h_s  = w_s + 3 * 128 * WST;      // [8][HST], swizzled
    float* u_s  = h_s + 8 * HST;            // swizzled
    float* r_s  = u_s + 8 * HST;            // swizzled
    float* zg_s = r_s + 8 * HST;            // swizzled
    float* xg_s = zg_s + 8 * HST;           // swizzled

    const int tid = threadIdx.x;
    const int b0 = blockIdx.x * 8;

    {
        const float* hw[3] = {huw, hrw, hgw};
        for (int mm = 0; mm < 3; mm++)
            for (int idx = tid; idx < 128 * 128; idx += 384) {
                int o = idx >> 7, k = idx & 127;
                w_s[(mm * 128 + o) * WST + HSWZ(k)] = hw[mm][idx];
            }
    }
    for (int idx = tid; idx < 8 * HST; idx += 384) h_s[idx] = 0.0f;

    const int wid = tid >> 5, lane = tid & 31;
    const int m = wid >> 2;
    const int c0 = (wid & 3) * 32;
    const int ks = lane & 3, cl = lane >> 2;
    const int cbase = c0 + cl * 4;
    const int csw = HSWZ(cbase);            // 4-aligned swizzled col base
    const int ra = ks, rb = ks + 4;

    const float* hb = (m == 0) ? hub : (m == 1) ? hrb : hgb;
    float bias[4];
    #pragma unroll
    for (int j = 0; j < 4; j++) bias[j] = hb[cbase + j];

    const float* wbase = &w_s[(m * 128 + cbase) * WST];
    const float* xrow_a = g_x + (size_t)m * BT * 128 + (size_t)(b0 + ra) * Tk * 128 + cbase;
    const float* xrow_b = g_x + (size_t)m * BT * 128 + (size_t)(b0 + rb) * Tk * 128 + cbase;
    const float* att_a = g_att + (size_t)(b0 + ra) * Tk;
    const float* att_b = g_att + (size_t)(b0 + rb) * Tk;

    __syncthreads();

    // software-pipelined x/att: preload t=0
    float4 xa = *(const float4*)(xrow_a);
    float4 xb = *(const float4*)(xrow_b);
    float atta = (m == 0) ? att_a[0] : 0.f;
    float attb = (m == 0) ? att_b[0] : 0.f;

    for (int t = 0; t < Tk; t++) {
        float4 xa_n, xb_n;
        float atta_n = 0.f, attb_n = 0.f;
        if (t + 1 < Tk) {
            xa_n = *(const float4*)(xrow_a + (size_t)(t + 1) * 128);
            xb_n = *(const float4*)(xrow_b + (size_t)(t + 1) * 128);
            if (m == 0) { atta_n = att_a[t + 1]; attb_n = att_b[t + 1]; }
        }

        u64 acc[4][8];
        #pragma unroll
        for (int j = 0; j < 4; j++)
            #pragma unroll
            for (int r = 0; r < 8; r++) acc[j][r] = 0ull;

        #pragma unroll 2
        for (int it = 0; it < 8; it++) {
            const int off = it * 16 + ks * 4;
            ulonglong2 h2[8];
            #pragma unroll
            for (int r = 0; r < 8; r++)
                h2[r] = *(const ulonglong2*)&h_s[r * HST + off];
            #pragma unroll
            for (int j = 0; j < 4; j++) {
                ulonglong2 w2 = *(const ulonglong2*)&wbase[j * WST + off];
                #pragma unroll
                for (int r = 0; r < 8; r++) {
                    acc[j][r] = ffma2(w2.x, h2[r].x, acc[j][r]);
                    acc[j][r] = ffma2(w2.y, h2[r].y, acc[j][r]);
                }
            }
        }

        float s[4][8];
        #pragma unroll
        for (int j = 0; j < 4; j++)
            #pragma unroll
            for (int r = 0; r < 8; r++) {
                float2 p = unpack2(acc[j][r]);
                s[j][r] = p.x + p.y;
                s[j][r] += __shfl_xor_sync(0xFFFFFFFFu, s[j][r], 1);
                s[j][r] += __shfl_xor_sync(0xFFFFFFFFu, s[j][r], 2);
            }

        float xav[4] = {xa.x, xa.y, xa.z, xa.w};
        float xbv[4] = {xb.x, xb.y, xb.z, xb.w};
        if (m == 0) {
            float4 oa, ob;
            float* pa = (float*)&oa; float* pb = (float*)&ob;
            #pragma unroll
            for (int j = 0; j < 4; j++) {
                pa[j] = __fdividef(atta, 1.0f + __expf(-(s[j][ra] + bias[j] + xav[j])));
                pb[j] = __fdividef(attb, 1.0f + __expf(-(s[j][rb] + bias[j] + xbv[j])));
            }
            *(float4*)&u_s[ra * HST + csw] = oa;
            *(float4*)&u_s[rb * HST + csw] = ob;
        } else if (m == 1) {
            float4 oa, ob;
            float* pa = (float*)&oa; float* pb = (float*)&ob;
            #pragma unroll
            for (int j = 0; j < 4; j++) {
                pa[j] = __fdividef(1.0f, 1.0f + __expf(-(s[j][ra] + bias[j] + xav[j])));
                pb[j] = __fdividef(1.0f, 1.0f + __expf(-(s[j][rb] + bias[j] + xbv[j])));
            }
            *(float4*)&r_s[ra * HST + csw] = oa;
            *(float4*)&r_s[rb * HST + csw] = ob;
        } else {
            float4 za, zb;
            float* qa = (float*)&za; float* qb = (float*)&zb;
            #pragma unroll
            for (int j = 0; j < 4; j++) {
                qa[j] = s[j][ra] + bias[j];
                qb[j] = s[j][rb] + bias[j];
            }
            *(float4*)&zg_s[ra * HST + csw] = za;
            *(float4*)&zg_s[rb * HST + csw] = zb;
            *(float4*)&xg_s[ra * HST + csw] = xa;
            *(float4*)&xg_s[rb * HST + csw] = xb;
        }
        __syncthreads();

        // combine on PHYSICAL indices (all arrays share the swizzle):
        // g = tanh(xg + r*zg); h += u*(g - h)
        for (int idx = tid; idx < 1024; idx += 384) {
            int row = idx >> 7, p = idx & 127;
            int pp = row * HST + p;
            float g = tanhf(xg_s[pp] + r_s[pp] * zg_s[pp]);
            float h = h_s[pp];
            h_s[pp] = h + u_s[pp] * (g - h);
        }
        __syncthreads();

        xa = xa_n; xb = xb_n; atta = atta_n; attb = attb_n;
    }

    // ---- final: out = concat(h, targets[:,0]) @ ln2_w^T + ln2_b ----
    for (int idx = tid; idx < 8 * 128; idx += 384)
        r_s[(idx >> 7) * HST + (idx & 127)] =
            targets[(size_t)((b0 + (idx >> 7)) * Tk) * 128 + (idx & 127)];  // plain layout
    float* lw = w_s;   // [256 k][LNS] transposed
    for (int idx = tid; idx < 128 * 256; idx += 384) {
        int o = idx >> 8, k2 = idx & 255;
        lw[k2 * LNS + o] = ln2w[idx];
    }
    __syncthreads();

    if (tid < 128) {
        const int o = tid;
        float acc2[8];
        const float b2 = ln2b[o];
        #pragma unroll
        for (int i = 0; i < 8; i++) acc2[i] = b2;
        #pragma unroll 2
        for (int k = 0; k < 128; k++) {
            float wh = lw[k * LNS + o];
            float wt = lw[(128 + k) * LNS + o];
            int hk = HSWZ(k);
            #pragma unroll
            for (int i = 0; i < 8; i++)
                acc2[i] += h_s[i * HST + hk] * wh + r_s[i * HST + k] * wt;
        }
        #pragma unroll
        for (int i = 0; i < 8; i++)
            out[(size_t)(b0 + i) * 128 + o] = acc2[i];
    }
}

// ---------------------------------------------------------------------------
extern "C" void kernel_launch(void* const* d_in, const int* in_sizes, int n_in,
                              void* d_out, int out_size)
{
    const float* targets = (const float*)d_in[0];
    const float* history = (const float*)d_in[1];
    const float* Ww  = (const float*)d_in[2];
    const float* Wb  = (const float*)d_in[3];
    const float* xuw = (const float*)d_in[4];
    const float* xub = (const float*)d_in[5];
    const float* huw = (const float*)d_in[6];
    const float* hub = (const float*)d_in[7];
    const float* xrw = (const float*)d_in[8];
    const float* xrb = (const float*)d_in[9];
    const float* hrw = (const float*)d_in[10];
    const float* hrb = (const float*)d_in[11];
    const float* xgw = (const float*)d_in[12];
    const float* xgb = (const float*)d_in[13];
    const float* hgw = (const float*)d_in[14];
    const float* hgb = (const float*)d_in[15];
    const float* ln2w = (const float*)d_in[16];
    const float* ln2b = (const float*)d_in[17];
    float* out = (float*)d_out;

    const size_t smA = (size_t)(3 * 128 * PJ) * sizeof(float);
    const size_t smC = (size_t)(3 * 128 * WST + 5 * 8 * HST) * sizeof(float);

    cudaFuncSetAttribute(proj_kernel, cudaFuncAttributeMaxDynamicSharedMemorySize, (int)smA);
    cudaFuncSetAttribute(scan_kernel, cudaFuncAttributeMaxDynamicSharedMemorySize, (int)smC);

    proj_kernel<<<NSLOT * 4, 512, smA>>>(targets, history, Ww, Wb,
                                         xuw, xub, xrw, xrb, xgw, xgb);
    score_softmax_kernel<<<Bk, 256>>>(history);
    scan_kernel<<<Bk / 8, 384, smC>>>(targets, huw, hub, hrw, hrb, hgw, hgb,
                                      ln2w, ln2b, out);
}

// round 7
// speedup vs baseline: 1.5094x; 1.1064x over previous
#include <cuda_runtime.h>
#include <cuda_bf16.h>
#include <math.h>
#include <stdint.h>

#define Bk 1024
#define Tk 200
#define BT (1024*200)
#define NTILE 1600        // BT/128
#define NSLOT 148

#define WST 132   // scan weight row stride
#define HST 132   // scan state row stride
#define LNS 130   // final-linear stride

// scan k-swizzle: k = ks*32 + it*4 + j  ->  phys = it*16 + ks*4 + j
#define HSWZ(k) ((((k) & 28) << 2) + (((k) >> 5) << 2) + ((k) & 3))

__device__ float g_x[3ull * BT * 128];  // xu, xr, xg projections
__device__ float g_s[BT];               // attention scores
__device__ float g_att[BT];             // softmax weights

typedef unsigned long long u64;

__device__ __forceinline__ u64 ffma2(u64 a, u64 b, u64 c) {
    u64 d;
    asm("fma.rn.f32x2 %0, %1, %2, %3;" : "=l"(d) : "l"(a), "l"(b), "l"(c));
    return d;
}
__device__ __forceinline__ float2 unpack2(u64 v) {
    float2 r;
    asm("mov.b64 {%0, %1}, %2;" : "=f"(r.x), "=f"(r.y) : "l"(v));
    return r;
}

// ===========================================================================
// mma.sync bf16 helpers (base PTX — compiles for compute_103)
// ===========================================================================
__device__ __forceinline__ void ldsm_x4(uint32_t addr, uint32_t& r0, uint32_t& r1,
                                        uint32_t& r2, uint32_t& r3) {
    asm volatile("ldmatrix.sync.aligned.m8n8.x4.shared.b16 {%0,%1,%2,%3}, [%4];"
                 : "=r"(r0), "=r"(r1), "=r"(r2), "=r"(r3) : "r"(addr));
}
__device__ __forceinline__ void mma16816(float* d, uint32_t a0, uint32_t a1,
                                         uint32_t a2, uint32_t a3,
                                         uint32_t b0, uint32_t b1) {
    asm volatile("mma.sync.aligned.m16n8k16.row.col.f32.bf16.bf16.f32 "
                 "{%0,%1,%2,%3}, {%4,%5,%6,%7}, {%8,%9}, {%0,%1,%2,%3};"
                 : "+f"(d[0]), "+f"(d[1]), "+f"(d[2]), "+f"(d[3])
                 : "r"(a0), "r"(a1), "r"(a2), "r"(a3), "r"(b0), "r"(b1));
}
__device__ __forceinline__ uint32_t pack_bf16(float f0, float f1) {
    uint16_t h0 = __bfloat16_as_ushort(__float2bfloat16_rn(f0));
    uint16_t h1 = __bfloat16_as_ushort(__float2bfloat16_rn(f1));
    return (uint32_t)h0 | ((uint32_t)h1 << 16);
}

// bf16 tile stride: 136 bf16 = 272 B = 17 x 16B  (ldmatrix conflict-free)
#define BFS 136
#define TILEB (128 * BFS * 2)          // 34816 B per bf16 tile

// smem byte layout for proj (total ~144 KB)
#define SM_WHI  0
#define SM_WLO  (SM_WHI + TILEB)
#define SM_AHI  (SM_WLO + TILEB)
#define SM_ALO  (SM_AHI + TILEB)
#define SM_BIAS (SM_ALO + TILEB)       // 128 floats
#define SM_RED  (SM_BIAS + 512)        // 128 x 8 floats
#define SM_TOT  (SM_RED + 4096)

// ---------------------------------------------------------------------------
// Kernel A: split-bf16 mma.sync projection GEMMs. 592 CTAs = 148 slots x 4.
//   grp=0: score s[b,t] = dot(targets@Ww^T + Wb, history[b,t,:])
//   grp=1..3: g_x[grp-1] = history @ {xu,xr,xg}_w^T + bias
// 512 threads = 16 warps; warp (wr,wc) owns a 32x32 sub-tile.
// D = Ah*Wh + Ah*Wl + Al*Wh accumulated in fp32 fragments (3 passes).
// ---------------------------------------------------------------------------
__global__ __launch_bounds__(512)
void proj_mma_kernel(const float* __restrict__ targets,
                     const float* __restrict__ history,
                     const float* __restrict__ Ww,  const float* __restrict__ Wb,
                     const float* __restrict__ xuw, const float* __restrict__ xub,
                     const float* __restrict__ xrw, const float* __restrict__ xrb,
                     const float* __restrict__ xgw, const float* __restrict__ xgb)
{
    extern __shared__ char smc[];
    const uint32_t sb = (uint32_t)__cvta_generic_to_shared(smc);
    float* bias_sm = (float*)(smc + SM_BIAS);
    float* red = (float*)(smc + SM_RED);

    const int tid = threadIdx.x;
    const int lane = tid & 31;
    const int wid = tid >> 5;
    const int grp = blockIdx.x & 3;
    const int slot = blockIdx.x >> 2;

    const float* wsrc = (grp == 0) ? Ww : (grp == 1) ? xuw : (grp == 2) ? xrw : xgw;
    const float* bsrc = (grp == 0) ? Wb : (grp == 1) ? xub : (grp == 2) ? xrb : xgb;
    const float* asrc = (grp == 0) ? targets : history;
    float* dstbase = (grp == 0) ? (float*)0 : (g_x + (size_t)(grp - 1) * BT * 128);

    // ---- stage + split weights once: row = tid/4, k0 = (tid%4)*32 ----
    const int srow = tid >> 2;
    const int sk0 = (tid & 3) * 32;
    {
        const float* src = wsrc + (size_t)srow * 128 + sk0;
        char* whi = smc + SM_WHI + (size_t)srow * (BFS * 2) + sk0 * 2;
        char* wlo = smc + SM_WLO + (size_t)srow * (BFS * 2) + sk0 * 2;
        #pragma unroll
        for (int i = 0; i < 8; i++) {
            float4 v = *(const float4*)(src + i * 4);
            float hx = __bfloat162float(__float2bfloat16_rn(v.x));
            float hy = __bfloat162float(__float2bfloat16_rn(v.y));
            float hz = __bfloat162float(__float2bfloat16_rn(v.z));
            float hw = __bfloat162float(__float2bfloat16_rn(v.w));
            uint2 ph = make_uint2(pack_bf16(v.x, v.y), pack_bf16(v.z, v.w));
            uint2 pl = make_uint2(pack_bf16(v.x - hx, v.y - hy),
                                  pack_bf16(v.z - hz, v.w - hw));
            *(uint2*)(whi + i * 8) = ph;
            *(uint2*)(wlo + i * 8) = pl;
        }
        if (tid < 128) bias_sm[tid] = bsrc[tid];
    }

    // warp tile coords
    const int wr = wid >> 2;          // 0..3 -> rows 32*wr
    const int wc = wid & 3;           // 0..3 -> cols 32*wc

    // ldmatrix lane address components (element offsets within a tile)
    // A (x4, 16x16): row = 32*wr + 16*mt + (lane&15); colhalf = lane>>4
    const int a_row_l = (lane & 15);
    const int a_ch = (lane >> 4);     // 0/1 -> +16B
    // B (x4, 2 n-tiles of 8): row = 32*wc + 16*np + (lane&7) + (lane>=16 ? 8:0)
    const int b_row_l = (lane & 7) + ((lane >> 4) << 3);
    const int b_ch = ((lane >> 3) & 1);

    // prefetch first A tile into registers
    int tile = slot;
    float4 pf[8];
    if (tile < NTILE) {
        const float* src = asrc + ((size_t)tile * 128 + srow) * 128 + sk0;
        #pragma unroll
        for (int i = 0; i < 8; i++) pf[i] = *(const float4*)(src + i * 4);
    }
    __syncthreads();   // weights staged

    for (; tile < NTILE; tile += NSLOT) {
        // ---- convert prefetched A to bf16 hi/lo in smem ----
        {
            char* ahi = smc + SM_AHI + (size_t)srow * (BFS * 2) + sk0 * 2;
            char* alo = smc + SM_ALO + (size_t)srow * (BFS * 2) + sk0 * 2;
            #pragma unroll
            for (int i = 0; i < 8; i++) {
                float4 v = pf[i];
                float hx = __bfloat162float(__float2bfloat16_rn(v.x));
                float hy = __bfloat162float(__float2bfloat16_rn(v.y));
                float hz = __bfloat162float(__float2bfloat16_rn(v.z));
                float hw = __bfloat162float(__float2bfloat16_rn(v.w));
                uint2 ph = make_uint2(pack_bf16(v.x, v.y), pack_bf16(v.z, v.w));
                uint2 pl = make_uint2(pack_bf16(v.x - hx, v.y - hy),
                                      pack_bf16(v.z - hz, v.w - hw));
                *(uint2*)(ahi + i * 8) = ph;
                *(uint2*)(alo + i * 8) = pl;
            }
        }
        __syncthreads();

        // ---- prefetch next tile (latency hidden behind MMA) ----
        {
            int nxt = tile + NSLOT;
            if (nxt < NTILE) {
                const float* src = asrc + ((size_t)nxt * 128 + srow) * 128 + sk0;
                #pragma unroll
                for (int i = 0; i < 8; i++) pf[i] = *(const float4*)(src + i * 4);
            }
        }

        // ---- MMA: 3 passes (AhWh, AhWl, AlWh), k-steps of 16 ----
        float c[2][4][4];
        #pragma unroll
        for (int mt = 0; mt < 2; mt++)
            #pragma unroll
            for (int nt = 0; nt < 4; nt++)
                #pragma unroll
                for (int q = 0; q < 4; q++) c[mt][nt][q] = 0.0f;

        #pragma unroll
        for (int pass = 0; pass < 3; pass++) {
            const uint32_t abase = sb + ((pass == 2) ? SM_ALO : SM_AHI);
            const uint32_t bbase = sb + ((pass == 1) ? SM_WLO : SM_WHI);
            const uint32_t aaddr0 = abase + (uint32_t)(32 * wr + a_row_l) * (BFS * 2) + a_ch * 16;
            const uint32_t baddr0 = bbase + (uint32_t)(32 * wc + b_row_l) * (BFS * 2) + b_ch * 16;

            #pragma unroll
            for (int ks = 0; ks < 8; ks++) {
                const uint32_t koff = (uint32_t)ks * 32;   // 16 bf16 = 32 B
                uint32_t a[2][4], b[2][4];
                #pragma unroll
                for (int mt = 0; mt < 2; mt++)
                    ldsm_x4(aaddr0 + (uint32_t)(16 * mt) * (BFS * 2) + koff,
                            a[mt][0], a[mt][1], a[mt][2], a[mt][3]);
                #pragma unroll
                for (int np = 0; np < 2; np++)
                    ldsm_x4(baddr0 + (uint32_t)(16 * np) * (BFS * 2) + koff,
                            b[np][0], b[np][1], b[np][2], b[np][3]);
                #pragma unroll
                for (int mt = 0; mt < 2; mt++) {
                    mma16816(c[mt][0], a[mt][0], a[mt][1], a[mt][2], a[mt][3], b[0][0], b[0][1]);
                    mma16816(c[mt][1], a[mt][0], a[mt][1], a[mt][2], a[mt][3], b[0][2], b[0][3]);
                    mma16816(c[mt][2], a[mt][0], a[mt][1], a[mt][2], a[mt][3], b[1][0], b[1][1]);
                    mma16816(c[mt][3], a[mt][0], a[mt][1], a[mt][2], a[mt][3], b[1][2], b[1][3]);
                }
            }
        }

        // ---- epilogue ----
        const int gid = lane >> 2, tg = lane & 3;
        float2 bias2[4];
        #pragma unroll
        for (int nt = 0; nt < 4; nt++)
            bias2[nt] = *(const float2*)&bias_sm[32 * wc + 8 * nt + 2 * tg];

        if (grp == 0) {
            // score: partial dot of (D + bias) with history over this warp's cols
            float p[4] = {0.f, 0.f, 0.f, 0.f};   // rows: gid, gid+8, 16+gid, 24+gid
            #pragma unroll
            for (int mt = 0; mt < 2; mt++) {
                const size_t r1 = (size_t)tile * 128 + 32 * wr + 16 * mt + gid;
                const size_t r2 = r1 + 8;
                #pragma unroll
                for (int nt = 0; nt < 4; nt++) {
                    const int cidx = 32 * wc + 8 * nt + 2 * tg;
                    float2 h1 = *(const float2*)(history + r1 * 128 + cidx);
                    float2 h2 = *(const float2*)(history + r2 * 128 + cidx);
                    p[2 * mt]     += (c[mt][nt][0] + bias2[nt].x) * h1.x
                                   + (c[mt][nt][1] + bias2[nt].y) * h1.y;
                    p[2 * mt + 1] += (c[mt][nt][2] + bias2[nt].x) * h2.x
                                   + (c[mt][nt][3] + bias2[nt].y) * h2.y;
                }
            }
            #pragma unroll
            for (int q = 0; q < 4; q++) {
                p[q] += __shfl_xor_sync(0xFFFFFFFFu, p[q], 1);
                p[q] += __shfl_xor_sync(0xFFFFFFFFu, p[q], 2);
            }
            if (tg == 0) {
                red[(32 * wr + gid) * 8 + wc]      = p[0];
                red[(32 * wr + gid + 8) * 8 + wc]  = p[1];
                red[(32 * wr + gid + 16) * 8 + wc] = p[2];
                red[(32 * wr + gid + 24) * 8 + wc] = p[3];
            }
            __syncthreads();
            if (tid < 128) {
                g_s[(size_t)tile * 128 + tid] = red[tid * 8 + 0] + red[tid * 8 + 1]
                                              + red[tid * 8 + 2] + red[tid * 8 + 3];
            }
        } else {
            #pragma unroll
            for (int mt = 0; mt < 2; mt++) {
                const size_t r1 = (size_t)tile * 128 + 32 * wr + 16 * mt + gid;
                const size_t r2 = r1 + 8;
                #pragma unroll
                for (int nt = 0; nt < 4; nt++) {
                    const int cidx = 32 * wc + 8 * nt + 2 * tg;
                    float2 v1 = make_float2(c[mt][nt][0] + bias2[nt].x,
                                            c[mt][nt][1] + bias2[nt].y);
                    float2 v2 = make_float2(c[mt][nt][2] + bias2[nt].x,
                                            c[mt][nt][3] + bias2[nt].y);
                    *(float2*)(dstbase + r1 * 128 + cidx) = v1;
                    *(float2*)(dstbase + r2 * 128 + cidx) = v2;
                }
            }
        }
        __syncthreads();   // A smem reusable next iteration
    }
}

// ---------------------------------------------------------------------------
// Kernel B: softmax over T per batch row (reads g_s).
// ---------------------------------------------------------------------------
__global__ void softmax_kernel()
{
    __shared__ float red[256];
    const int b = blockIdx.x;
    const int tid = threadIdx.x;

    float v = (tid < Tk) ? g_s[(size_t)b * Tk + tid] : -1e30f;
    red[tid] = v;
    __syncthreads();
    for (int s = 128; s > 0; s >>= 1) {
        if (tid < s) red[tid] = fmaxf(red[tid], red[tid + s]);
        __syncthreads();
    }
    const float mx = red[0];
    __syncthreads();
    float e = (tid < Tk) ? __expf(v - mx) : 0.0f;
    red[tid] = e;
    __syncthreads();
    for (int s = 128; s > 0; s >>= 1) {
        if (tid < s) red[tid] += red[tid + s];
        __syncthreads();
    }
    const float inv = 1.0f / red[0];
    if (tid < Tk) g_att[(size_t)b * Tk + tid] = e * inv;
}

// ---------------------------------------------------------------------------
// Kernel C: persistent scan (unchanged from round 5 — passing version).
// ---------------------------------------------------------------------------
__global__ __launch_bounds__(384)
void scan_kernel(const float* __restrict__ targets,
                 const float* __restrict__ huw, const float* __restrict__ hub,
                 const float* __restrict__ hrw, const float* __restrict__ hrb,
                 const float* __restrict__ hgw, const float* __restrict__ hgb,
                 const float* __restrict__ ln2w, const float* __restrict__ ln2b,
                 float* __restrict__ out)
{
    extern __shared__ float sm[];
    float* w_s  = sm;                       // [3*128][WST], swizzled k
    float* h_s  = w_s + 3 * 128 * WST;      // [8][HST], swizzled
    float* u_s  = h_s + 8 * HST;
    float* r_s  = u_s + 8 * HST;
    float* zg_s = r_s + 8 * HST;
    float* xg_s = zg_s + 8 * HST;

    const int tid = threadIdx.x;
    const int b0 = blockIdx.x * 8;

    {
        const float* hw[3] = {huw, hrw, hgw};
        for (int mm = 0; mm < 3; mm++)
            for (int idx = tid; idx < 128 * 128; idx += 384) {
                int o = idx >> 7, k = idx & 127;
                w_s[(mm * 128 + o) * WST + HSWZ(k)] = hw[mm][idx];
            }
    }
    for (int idx = tid; idx < 8 * HST; idx += 384) h_s[idx] = 0.0f;

    const int wid = tid >> 5, lane = tid & 31;
    const int m = wid >> 2;
    const int c0 = (wid & 3) * 32;
    const int ks = lane & 3, cl = lane >> 2;
    const int cbase = c0 + cl * 4;
    const int csw = HSWZ(cbase);
    const int ra = ks, rb = ks + 4;

    const float* hb = (m == 0) ? hub : (m == 1) ? hrb : hgb;
    float bias[4];
    #pragma unroll
    for (int j = 0; j < 4; j++) bias[j] = hb[cbase + j];

    const float* wbase = &w_s[(m * 128 + cbase) * WST];
    const float* xrow_a = g_x + (size_t)m * BT * 128 + (size_t)(b0 + ra) * Tk * 128 + cbase;
    const float* xrow_b = g_x + (size_t)m * BT * 128 + (size_t)(b0 + rb) * Tk * 128 + cbase;
    const float* att_a = g_att + (size_t)(b0 + ra) * Tk;
    const float* att_b = g_att + (size_t)(b0 + rb) * Tk;

    __syncthreads();

    float4 xa = *(const float4*)(xrow_a);
    float4 xb = *(const float4*)(xrow_b);
    float atta = (m == 0) ? att_a[0] : 0.f;
    float attb = (m == 0) ? att_b[0] : 0.f;

    for (int t = 0; t < Tk; t++) {
        float4 xa_n, xb_n;
        float atta_n = 0.f, attb_n = 0.f;
        if (t + 1 < Tk) {
            xa_n = *(const float4*)(xrow_a + (size_t)(t + 1) * 128);
            xb_n = *(const float4*)(xrow_b + (size_t)(t + 1) * 128);
            if (m == 0) { atta_n = att_a[t + 1]; attb_n = att_b[t + 1]; }
        }

        u64 acc[4][8];
        #pragma unroll
        for (int j = 0; j < 4; j++)
            #pragma unroll
            for (int r = 0; r < 8; r++) acc[j][r] = 0ull;

        #pragma unroll 2
        for (int it = 0; it < 8; it++) {
            const int off = it * 16 + ks * 4;
            ulonglong2 h2[8];
            #pragma unroll
            for (int r = 0; r < 8; r++)
                h2[r] = *(const ulonglong2*)&h_s[r * HST + off];
            #pragma unroll
            for (int j = 0; j < 4; j++) {
                ulonglong2 w2 = *(const ulonglong2*)&wbase[j * WST + off];
                #pragma unroll
                for (int r = 0; r < 8; r++) {
                    acc[j][r] = ffma2(w2.x, h2[r].x, acc[j][r]);
                    acc[j][r] = ffma2(w2.y, h2[r].y, acc[j][r]);
                }
            }
        }

        float s[4][8];
        #pragma unroll
        for (int j = 0; j < 4; j++)
            #pragma unroll
            for (int r = 0; r < 8; r++) {
                float2 p = unpack2(acc[j][r]);
                s[j][r] = p.x + p.y;
                s[j][r] += __shfl_xor_sync(0xFFFFFFFFu, s[j][r], 1);
                s[j][r] += __shfl_xor_sync(0xFFFFFFFFu, s[j][r], 2);
            }

        float xav[4] = {xa.x, xa.y, xa.z, xa.w};
        float xbv[4] = {xb.x, xb.y, xb.z, xb.w};
        if (m == 0) {
            float4 oa, ob;
            float* pa = (float*)&oa; float* pb = (float*)&ob;
            #pragma unroll
            for (int j = 0; j < 4; j++) {
                pa[j] = __fdividef(atta, 1.0f + __expf(-(s[j][ra] + bias[j] + xav[j])));
                pb[j] = __fdividef(attb, 1.0f + __expf(-(s[j][rb] + bias[j] + xbv[j])));
            }
            *(float4*)&u_s[ra * HST + csw] = oa;
            *(float4*)&u_s[rb * HST + csw] = ob;
        } else if (m == 1) {
            float4 oa, ob;
            float* pa = (float*)&oa; float* pb = (float*)&ob;
            #pragma unroll
            for (int j = 0; j < 4; j++) {
                pa[j] = __fdividef(1.0f, 1.0f + __expf(-(s[j][ra] + bias[j] + xav[j])));
                pb[j] = __fdividef(1.0f, 1.0f + __expf(-(s[j][rb] + bias[j] + xbv[j])));
            }
            *(float4*)&r_s[ra * HST + csw] = oa;
            *(float4*)&r_s[rb * HST + csw] = ob;
        } else {
            float4 za, zb;
            float* qa = (float*)&za; float* qb = (float*)&zb;
            #pragma unroll
            for (int j = 0; j < 4; j++) {
                qa[j] = s[j][ra] + bias[j];
                qb[j] = s[j][rb] + bias[j];
            }
            *(float4*)&zg_s[ra * HST + csw] = za;
            *(float4*)&zg_s[rb * HST + csw] = zb;
            *(float4*)&xg_s[ra * HST + csw] = xa;
            *(float4*)&xg_s[rb * HST + csw] = xb;
        }
        __syncthreads();

        for (int idx = tid; idx < 1024; idx += 384) {
            int rw = idx >> 7, p = idx & 127;
            int pp = rw * HST + p;
            float g = tanhf(xg_s[pp] + r_s[pp] * zg_s[pp]);
            float h = h_s[pp];
            h_s[pp] = h + u_s[pp] * (g - h);
        }
        __syncthreads();

        xa = xa_n; xb = xb_n; atta = atta_n; attb = attb_n;
    }

    // final linear
    for (int idx = tid; idx < 8 * 128; idx += 384)
        r_s[(idx >> 7) * HST + (idx & 127)] =
            targets[(size_t)((b0 + (idx >> 7)) * Tk) * 128 + (idx & 127)];
    float* lw = w_s;
    for (int idx = tid; idx < 128 * 256; idx += 384) {
        int o = idx >> 8, k2 = idx & 255;
        lw[k2 * LNS + o] = ln2w[idx];
    }
    __syncthreads();

    if (tid < 128) {
        const int o = tid;
        float acc2[8];
        const float b2 = ln2b[o];
        #pragma unroll
        for (int i = 0; i < 8; i++) acc2[i] = b2;
        #pragma unroll 2
        for (int k = 0; k < 128; k++) {
            float wh = lw[k * LNS + o];
            float wt = lw[(128 + k) * LNS + o];
            int hk = HSWZ(k);
            #pragma unroll
            for (int i = 0; i < 8; i++)
                acc2[i] += h_s[i * HST + hk] * wh + r_s[i * HST + k] * wt;
        }
        #pragma unroll
        for (int i = 0; i < 8; i++)
            out[(size_t)(b0 + i) * 128 + o] = acc2[i];
    }
}

// ---------------------------------------------------------------------------
extern "C" void kernel_launch(void* const* d_in, const int* in_sizes, int n_in,
                              void* d_out, int out_size)
{
    const float* targets = (const float*)d_in[0];
    const float* history = (const float*)d_in[1];
    const float* Ww  = (const float*)d_in[2];
    const float* Wb  = (const float*)d_in[3];
    const float* xuw = (const float*)d_in[4];
    const float* xub = (const float*)d_in[5];
    const float* huw = (const float*)d_in[6];
    const float* hub = (const float*)d_in[7];
    const float* xrw = (const float*)d_in[8];
    const float* xrb = (const float*)d_in[9];
    const float* hrw = (const float*)d_in[10];
    const float* hrb = (const float*)d_in[11];
    const float* xgw = (const float*)d_in[12];
    const float* xgb = (const float*)d_in[13];
    const float* hgw = (const float*)d_in[14];
    const float* hgb = (const float*)d_in[15];
    const float* ln2w = (const float*)d_in[16];
    const float* ln2b = (const float*)d_in[17];
    float* out = (float*)d_out;

    const size_t smC = (size_t)(3 * 128 * WST + 5 * 8 * HST) * sizeof(float);

    cudaFuncSetAttribute(proj_mma_kernel, cudaFuncAttributeMaxDynamicSharedMemorySize, SM_TOT);
    cudaFuncSetAttribute(scan_kernel, cudaFuncAttributeMaxDynamicSharedMemorySize, (int)smC);

    proj_mma_kernel<<<NSLOT * 4, 512, SM_TOT>>>(targets, history, Ww, Wb,
                                                xuw, xub, xrw, xrb, xgw, xgb);
    softmax_kernel<<<Bk, 256>>>();
    scan_kernel<<<Bk / 8, 384, smC>>>(targets, huw, hub, hrw, hrb, hgw, hgb,
                                      ln2w, ln2b, out);
}

// round 8
// speedup vs baseline: 1.7296x; 1.1459x over previous
#include <cuda_runtime.h>
#include <cuda_bf16.h>
#include <math.h>
#include <stdint.h>

#define Bk 1024
#define Tk 200
#define BT (1024*200)

#define NTIL2 3200        // BT/64 row-tiles per group
#define NSL2  74          // persistent slots per group (296 CTAs total, 2/SM)

#define WST 132   // scan weight row stride
#define HST 132   // scan state row stride
#define LNS 130   // final-linear stride

// scan k-swizzle: k = ks*32 + it*4 + j  ->  phys = it*16 + ks*4 + j
#define HSWZ(k) ((((k) & 28) << 2) + (((k) >> 5) << 2) + ((k) & 3))

__device__ float g_x[3ull * BT * 128];  // xu, xr, xg projections
__device__ float g_s[BT];               // attention scores
__device__ float g_att[BT];             // softmax weights

typedef unsigned long long u64;

__device__ __forceinline__ u64 ffma2(u64 a, u64 b, u64 c) {
    u64 d;
    asm("fma.rn.f32x2 %0, %1, %2, %3;" : "=l"(d) : "l"(a), "l"(b), "l"(c));
    return d;
}
__device__ __forceinline__ float2 unpack2(u64 v) {
    float2 r;
    asm("mov.b64 {%0, %1}, %2;" : "=f"(r.x), "=f"(r.y) : "l"(v));
    return r;
}

// ===========================================================================
// mma.sync bf16 helpers (base PTX — compiles for compute_103)
// ===========================================================================
__device__ __forceinline__ void ldsm_x4(uint32_t addr, uint32_t& r0, uint32_t& r1,
                                        uint32_t& r2, uint32_t& r3) {
    asm volatile("ldmatrix.sync.aligned.m8n8.x4.shared.b16 {%0,%1,%2,%3}, [%4];"
                 : "=r"(r0), "=r"(r1), "=r"(r2), "=r"(r3) : "r"(addr));
}
__device__ __forceinline__ void mma16816(float* d, const uint32_t* a,
                                         uint32_t b0, uint32_t b1) {
    asm volatile("mma.sync.aligned.m16n8k16.row.col.f32.bf16.bf16.f32 "
                 "{%0,%1,%2,%3}, {%4,%5,%6,%7}, {%8,%9}, {%0,%1,%2,%3};"
                 : "+f"(d[0]), "+f"(d[1]), "+f"(d[2]), "+f"(d[3])
                 : "r"(a[0]), "r"(a[1]), "r"(a[2]), "r"(a[3]), "r"(b0), "r"(b1));
}
__device__ __forceinline__ uint32_t pack_bf16(float f0, float f1) {
    uint16_t h0 = __bfloat16_as_ushort(__float2bfloat16_rn(f0));
    uint16_t h1 = __bfloat16_as_ushort(__float2bfloat16_rn(f1));
    return (uint32_t)h0 | ((uint32_t)h1 << 16);
}
__device__ __forceinline__ void split_sts(char* hi, char* lo, int byteoff, float4 v) {
    float hx = __bfloat162float(__float2bfloat16_rn(v.x));
    float hy = __bfloat162float(__float2bfloat16_rn(v.y));
    float hz = __bfloat162float(__float2bfloat16_rn(v.z));
    float hw = __bfloat162float(__float2bfloat16_rn(v.w));
    *(uint2*)(hi + byteoff) = make_uint2(pack_bf16(v.x, v.y), pack_bf16(v.z, v.w));
    *(uint2*)(lo + byteoff) = make_uint2(pack_bf16(v.x - hx, v.y - hy),
                                         pack_bf16(v.z - hz, v.w - hw));
}

// bf16 tile stride: 136 bf16 = 272 B = 17 x 16B  (ldmatrix conflict-free)
#define BFS 136

// smem byte layout for proj (~105 KB -> 2 CTAs/SM)
#define SM_WHI  0
#define SM_WLO  (SM_WHI + 128 * BFS * 2)     // 34816
#define SM_AHI  (SM_WLO + 128 * BFS * 2)     // 69632
#define SM_ALO  (SM_AHI + 64 * BFS * 2)      // 87040
#define SM_BIAS (SM_ALO + 64 * BFS * 2)      // 104448
#define SM_RED  (SM_BIAS + 512)              // 104960; 64 x 8 floats
#define SM_TOT  (SM_RED + 2048)              // 107008

// ---------------------------------------------------------------------------
// Kernel A: split-bf16 mma.sync projection GEMMs.
// 296 persistent CTAs = 74 slots x 4 groups; 256 threads; tile 64 x 128;
// warp grid 2(wr) x 4(wc) of 32x32 subtiles; 2 CTAs/SM for overlap.
//   grp=0: score s[b,t] = dot(targets@Ww^T + Wb, history[b,t,:])
//   grp=1..3: g_x[grp-1] = history @ {xu,xr,xg}_w^T + bias
// D = Ah*Wh + Ah*Wl + Al*Wh accumulated in fp32 frags (fused k-loop).
// ---------------------------------------------------------------------------
__global__ __launch_bounds__(256, 2)
void proj_mma_kernel(const float* __restrict__ targets,
                     const float* __restrict__ history,
                     const float* __restrict__ Ww,  const float* __restrict__ Wb,
                     const float* __restrict__ xuw, const float* __restrict__ xub,
                     const float* __restrict__ xrw, const float* __restrict__ xrb,
                     const float* __restrict__ xgw, const float* __restrict__ xgb)
{
    extern __shared__ char smc[];
    const uint32_t sb = (uint32_t)__cvta_generic_to_shared(smc);
    float* bias_sm = (float*)(smc + SM_BIAS);
    float* red = (float*)(smc + SM_RED);

    const int tid = threadIdx.x;
    const int lane = tid & 31;
    const int wid = tid >> 5;
    const int grp = blockIdx.x & 3;
    const int slot = blockIdx.x >> 2;

    const float* wsrc = (grp == 0) ? Ww : (grp == 1) ? xuw : (grp == 2) ? xrw : xgw;
    const float* bsrc = (grp == 0) ? Wb : (grp == 1) ? xub : (grp == 2) ? xrb : xgb;
    const float* asrc = (grp == 0) ? targets : history;
    float* dstbase = (grp == 0) ? (float*)0 : (g_x + (size_t)(grp - 1) * BT * 128);

    // ---- stage + split weights once: row = tid/2, k0 = (tid&1)*64 ----
    {
        const int wrow = tid >> 1, wk0 = (tid & 1) * 64;
        const float* src = wsrc + (size_t)wrow * 128 + wk0;
        char* whi = smc + SM_WHI + (size_t)wrow * (BFS * 2) + wk0 * 2;
        char* wlo = smc + SM_WLO + (size_t)wrow * (BFS * 2) + wk0 * 2;
        #pragma unroll
        for (int i = 0; i < 16; i++)
            split_sts(whi, wlo, i * 8, *(const float4*)(src + i * 4));
        if (tid < 128) bias_sm[tid] = bsrc[tid];
    }

    // warp tile coords
    const int wr = wid >> 2;          // 0..1 -> rows 32*wr
    const int wc = wid & 3;           // 0..3 -> cols 32*wc

    // ldmatrix lane address components
    const int a_row_l = (lane & 15);
    const int a_ch = (lane >> 4);               // 0/1 -> +16B
    const int b_row_l = (lane & 7) + ((lane >> 4) << 3);
    const int b_ch = ((lane >> 3) & 1);

    // A staging coords: row = tid/4 (0..63), k0 = (tid&3)*32
    const int arow = tid >> 2, ak0 = (tid & 3) * 32;
    char* const ahi_st = smc + SM_AHI + (size_t)arow * (BFS * 2) + ak0 * 2;
    char* const alo_st = smc + SM_ALO + (size_t)arow * (BFS * 2) + ak0 * 2;

    // prefetch first A tile into registers
    int t = slot;
    float4 pf[8];
    if (t < NTIL2) {
        const float* src = asrc + ((size_t)t * 64 + arow) * 128 + ak0;
        #pragma unroll
        for (int i = 0; i < 8; i++) pf[i] = *(const float4*)(src + i * 4);
    }
    __syncthreads();   // weights staged

    const uint32_t aHi0 = sb + SM_AHI + (uint32_t)(32 * wr + a_row_l) * (BFS * 2) + a_ch * 16;
    const uint32_t aLo0 = sb + SM_ALO + (uint32_t)(32 * wr + a_row_l) * (BFS * 2) + a_ch * 16;
    const uint32_t bHi0 = sb + SM_WHI + (uint32_t)(32 * wc + b_row_l) * (BFS * 2) + b_ch * 16;
    const uint32_t bLo0 = sb + SM_WLO + (uint32_t)(32 * wc + b_row_l) * (BFS * 2) + b_ch * 16;

    for (; t < NTIL2; t += NSL2) {
        // ---- convert prefetched A to bf16 hi/lo in smem ----
        #pragma unroll
        for (int i = 0; i < 8; i++) split_sts(ahi_st, alo_st, i * 8, pf[i]);
        __syncthreads();

        // ---- prefetch next tile (hidden behind MMA) ----
        {
            int nxt = t + NSL2;
            if (nxt < NTIL2) {
                const float* src = asrc + ((size_t)nxt * 64 + arow) * 128 + ak0;
                #pragma unroll
                for (int i = 0; i < 8; i++) pf[i] = *(const float4*)(src + i * 4);
            }
        }

        // ---- fused MMA: per ks do AhWh, AhWl, AlWh ----
        float c[2][4][4];
        #pragma unroll
        for (int mt = 0; mt < 2; mt++)
            #pragma unroll
            for (int nt = 0; nt < 4; nt++)
                #pragma unroll
                for (int q = 0; q < 4; q++) c[mt][nt][q] = 0.0f;

        #pragma unroll
        for (int ks = 0; ks < 8; ks++) {
            const uint32_t koff = (uint32_t)ks * 32;     // 16 bf16 = 32 B
            uint32_t ah[2][4], bh[2][4], bl[2][4];
            #pragma unroll
            for (int mt = 0; mt < 2; mt++)
                ldsm_x4(aHi0 + (uint32_t)(16 * mt) * (BFS * 2) + koff,
                        ah[mt][0], ah[mt][1], ah[mt][2], ah[mt][3]);
            #pragma unroll
            for (int np = 0; np < 2; np++) {
                ldsm_x4(bHi0 + (uint32_t)(16 * np) * (BFS * 2) + koff,
                        bh[np][0], bh[np][1], bh[np][2], bh[np][3]);
                ldsm_x4(bLo0 + (uint32_t)(16 * np) * (BFS * 2) + koff,
                        bl[np][0], bl[np][1], bl[np][2], bl[np][3]);
            }
            // Ah * (Wh + Wl)
            #pragma unroll
            for (int mt = 0; mt < 2; mt++) {
                mma16816(c[mt][0], ah[mt], bh[0][0], bh[0][1]);
                mma16816(c[mt][0], ah[mt], bl[0][0], bl[0][1]);
                mma16816(c[mt][1], ah[mt], bh[0][2], bh[0][3]);
                mma16816(c[mt][1], ah[mt], bl[0][2], bl[0][3]);
                mma16816(c[mt][2], ah[mt], bh[1][0], bh[1][1]);
                mma16816(c[mt][2], ah[mt], bl[1][0], bl[1][1]);
                mma16816(c[mt][3], ah[mt], bh[1][2], bh[1][3]);
                mma16816(c[mt][3], ah[mt], bl[1][2], bl[1][3]);
            }
            // Al * Wh   (al loaded late so bl regs can retire)
            uint32_t al[2][4];
            #pragma unroll
            for (int mt = 0; mt < 2; mt++)
                ldsm_x4(aLo0 + (uint32_t)(16 * mt) * (BFS * 2) + koff,
                        al[mt][0], al[mt][1], al[mt][2], al[mt][3]);
            #pragma unroll
            for (int mt = 0; mt < 2; mt++) {
                mma16816(c[mt][0], al[mt], bh[0][0], bh[0][1]);
                mma16816(c[mt][1], al[mt], bh[0][2], bh[0][3]);
                mma16816(c[mt][2], al[mt], bh[1][0], bh[1][1]);
                mma16816(c[mt][3], al[mt], bh[1][2], bh[1][3]);
            }
        }

        // ---- epilogue ----
        const int gid = lane >> 2, tg = lane & 3;
        float2 bias2[4];
        #pragma unroll
        for (int nt = 0; nt < 4; nt++)
            bias2[nt] = *(const float2*)&bias_sm[32 * wc + 8 * nt + 2 * tg];

        if (grp == 0) {
            float p[4] = {0.f, 0.f, 0.f, 0.f};
            #pragma unroll
            for (int mt = 0; mt < 2; mt++) {
                const size_t r1 = (size_t)t * 64 + 32 * wr + 16 * mt + gid;
                const size_t r2 = r1 + 8;
                #pragma unroll
                for (int nt = 0; nt < 4; nt++) {
                    const int cidx = 32 * wc + 8 * nt + 2 * tg;
                    float2 h1 = *(const float2*)(history + r1 * 128 + cidx);
                    float2 h2 = *(const float2*)(history + r2 * 128 + cidx);
                    p[2 * mt]     += (c[mt][nt][0] + bias2[nt].x) * h1.x
                                   + (c[mt][nt][1] + bias2[nt].y) * h1.y;
                    p[2 * mt + 1] += (c[mt][nt][2] + bias2[nt].x) * h2.x
                                   + (c[mt][nt][3] + bias2[nt].y) * h2.y;
                }
            }
            #pragma unroll
            for (int q = 0; q < 4; q++) {
                p[q] += __shfl_xor_sync(0xFFFFFFFFu, p[q], 1);
                p[q] += __shfl_xor_sync(0xFFFFFFFFu, p[q], 2);
            }
            if (tg == 0) {
                red[(32 * wr + gid) * 8 + wc]      = p[0];
                red[(32 * wr + gid + 8) * 8 + wc]  = p[1];
                red[(32 * wr + gid + 16) * 8 + wc] = p[2];
                red[(32 * wr + gid + 24) * 8 + wc] = p[3];
            }
            __syncthreads();
            if (tid < 64) {
                g_s[(size_t)t * 64 + tid] = red[tid * 8 + 0] + red[tid * 8 + 1]
                                          + red[tid * 8 + 2] + red[tid * 8 + 3];
            }
        } else {
            #pragma unroll
            for (int mt = 0; mt < 2; mt++) {
                const size_t r1 = (size_t)t * 64 + 32 * wr + 16 * mt + gid;
                const size_t r2 = r1 + 8;
                #pragma unroll
                for (int nt = 0; nt < 4; nt++) {
                    const int cidx = 32 * wc + 8 * nt + 2 * tg;
                    *(float2*)(dstbase + r1 * 128 + cidx) =
                        make_float2(c[mt][nt][0] + bias2[nt].x, c[mt][nt][1] + bias2[nt].y);
                    *(float2*)(dstbase + r2 * 128 + cidx) =
                        make_float2(c[mt][nt][2] + bias2[nt].x, c[mt][nt][3] + bias2[nt].y);
                }
            }
        }
        __syncthreads();   // A smem + red reusable next iteration
    }
}

// ---------------------------------------------------------------------------
// Kernel B: softmax over T per batch row (reads g_s).
// ---------------------------------------------------------------------------
__global__ void softmax_kernel()
{
    __shared__ float red[256];
    const int b = blockIdx.x;
    const int tid = threadIdx.x;

    float v = (tid < Tk) ? g_s[(size_t)b * Tk + tid] : -1e30f;
    red[tid] = v;
    __syncthreads();
    for (int s = 128; s > 0; s >>= 1) {
        if (tid < s) red[tid] = fmaxf(red[tid], red[tid + s]);
        __syncthreads();
    }
    const float mx = red[0];
    __syncthreads();
    float e = (tid < Tk) ? __expf(v - mx) : 0.0f;
    red[tid] = e;
    __syncthreads();
    for (int s = 128; s > 0; s >>= 1) {
        if (tid < s) red[tid] += red[tid + s];
        __syncthreads();
    }
    const float inv = 1.0f / red[0];
    if (tid < Tk) g_att[(size_t)b * Tk + tid] = e * inv;
}

// ---------------------------------------------------------------------------
// Kernel C: persistent scan (unchanged — passing version).
// ---------------------------------------------------------------------------
__global__ __launch_bounds__(384)
void scan_kernel(const float* __restrict__ targets,
                 const float* __restrict__ huw, const float* __restrict__ hub,
                 const float* __restrict__ hrw, const float* __restrict__ hrb,
                 const float* __restrict__ hgw, const float* __restrict__ hgb,
                 const float* __restrict__ ln2w, const float* __restrict__ ln2b,
                 float* __restrict__ out)
{
    extern __shared__ float sm[];
    float* w_s  = sm;                       // [3*128][WST], swizzled k
    float* h_s  = w_s + 3 * 128 * WST;      // [8][HST], swizzled
    float* u_s  = h_s + 8 * HST;
    float* r_s  = u_s + 8 * HST;
    float* zg_s = r_s + 8 * HST;
    float* xg_s = zg_s + 8 * HST;

    const int tid = threadIdx.x;
    const int b0 = blockIdx.x * 8;

    {
        const float* hw[3] = {huw, hrw, hgw};
        for (int mm = 0; mm < 3; mm++)
            for (int idx = tid; idx < 128 * 128; idx += 384) {
                int o = idx >> 7, k = idx & 127;
                w_s[(mm * 128 + o) * WST + HSWZ(k)] = hw[mm][idx];
            }
    }
    for (int idx = tid; idx < 8 * HST; idx += 384) h_s[idx] = 0.0f;

    const int wid = tid >> 5, lane = tid & 31;
    const int m = wid >> 2;
    const int c0 = (wid & 3) * 32;
    const int ks = lane & 3, cl = lane >> 2;
    const int cbase = c0 + cl * 4;
    const int csw = HSWZ(cbase);
    const int ra = ks, rb = ks + 4;

    const float* hb = (m == 0) ? hub : (m == 1) ? hrb : hgb;
    float bias[4];
    #pragma unroll
    for (int j = 0; j < 4; j++) bias[j] = hb[cbase + j];

    const float* wbase = &w_s[(m * 128 + cbase) * WST];
    const float* xrow_a = g_x + (size_t)m * BT * 128 + (size_t)(b0 + ra) * Tk * 128 + cbase;
    const float* xrow_b = g_x + (size_t)m * BT * 128 + (size_t)(b0 + rb) * Tk * 128 + cbase;
    const float* att_a = g_att + (size_t)(b0 + ra) * Tk;
    const float* att_b = g_att + (size_t)(b0 + rb) * Tk;

    __syncthreads();

    float4 xa = *(const float4*)(xrow_a);
    float4 xb = *(const float4*)(xrow_b);
    float atta = (m == 0) ? att_a[0] : 0.f;
    float attb = (m == 0) ? att_b[0] : 0.f;

    for (int t = 0; t < Tk; t++) {
        float4 xa_n, xb_n;
        float atta_n = 0.f, attb_n = 0.f;
        if (t + 1 < Tk) {
            xa_n = *(const float4*)(xrow_a + (size_t)(t + 1) * 128);
            xb_n = *(const float4*)(xrow_b + (size_t)(t + 1) * 128);
            if (m == 0) { atta_n = att_a[t + 1]; attb_n = att_b[t + 1]; }
        }

        u64 acc[4][8];
        #pragma unroll
        for (int j = 0; j < 4; j++)
            #pragma unroll
            for (int r = 0; r < 8; r++) acc[j][r] = 0ull;

        #pragma unroll 2
        for (int it = 0; it < 8; it++) {
            const int off = it * 16 + ks * 4;
            ulonglong2 h2[8];
            #pragma unroll
            for (int r = 0; r < 8; r++)
                h2[r] = *(const ulonglong2*)&h_s[r * HST + off];
            #pragma unroll
            for (int j = 0; j < 4; j++) {
                ulonglong2 w2 = *(const ulonglong2*)&wbase[j * WST + off];
                #pragma unroll
                for (int r = 0; r < 8; r++) {
                    acc[j][r] = ffma2(w2.x, h2[r].x, acc[j][r]);
                    acc[j][r] = ffma2(w2.y, h2[r].y, acc[j][r]);
                }
            }
        }

        float s[4][8];
        #pragma unroll
        for (int j = 0; j < 4; j++)
            #pragma unroll
            for (int r = 0; r < 8; r++) {
                float2 p = unpack2(acc[j][r]);
                s[j][r] = p.x + p.y;
                s[j][r] += __shfl_xor_sync(0xFFFFFFFFu, s[j][r], 1);
                s[j][r] += __shfl_xor_sync(0xFFFFFFFFu, s[j][r], 2);
            }

        float xav[4] = {xa.x, xa.y, xa.z, xa.w};
        float xbv[4] = {xb.x, xb.y, xb.z, xb.w};
        if (m == 0) {
            float4 oa, ob;
            float* pa = (float*)&oa; float* pb = (float*)&ob;
            #pragma unroll
            for (int j = 0; j < 4; j++) {
                pa[j] = __fdividef(atta, 1.0f + __expf(-(s[j][ra] + bias[j] + xav[j])));
                pb[j] = __fdividef(attb, 1.0f + __expf(-(s[j][rb] + bias[j] + xbv[j])));
            }
            *(float4*)&u_s[ra * HST + csw] = oa;
            *(float4*)&u_s[rb * HST + csw] = ob;
        } else if (m == 1) {
            float4 oa, ob;
            float* pa = (float*)&oa; float* pb = (float*)&ob;
            #pragma unroll
            for (int j = 0; j < 4; j++) {
                pa[j] = __fdividef(1.0f, 1.0f + __expf(-(s[j][ra] + bias[j] + xav[j])));
                pb[j] = __fdividef(1.0f, 1.0f + __expf(-(s[j][rb] + bias[j] + xbv[j])));
            }
            *(float4*)&r_s[ra * HST + csw] = oa;
            *(float4*)&r_s[rb * HST + csw] = ob;
        } else {
            float4 za, zb;
            float* qa = (float*)&za; float* qb = (float*)&zb;
            #pragma unroll
            for (int j = 0; j < 4; j++) {
                qa[j] = s[j][ra] + bias[j];
                qb[j] = s[j][rb] + bias[j];
            }
            *(float4*)&zg_s[ra * HST + csw] = za;
            *(float4*)&zg_s[rb * HST + csw] = zb;
            *(float4*)&xg_s[ra * HST + csw] = xa;
            *(float4*)&xg_s[rb * HST + csw] = xb;
        }
        __syncthreads();

        for (int idx = tid; idx < 1024; idx += 384) {
            int rw = idx >> 7, p = idx & 127;
            int pp = rw * HST + p;
            float g = tanhf(xg_s[pp] + r_s[pp] * zg_s[pp]);
            float h = h_s[pp];
            h_s[pp] = h + u_s[pp] * (g - h);
        }
        __syncthreads();

        xa = xa_n; xb = xb_n; atta = atta_n; attb = attb_n;
    }

    // final linear
    for (int idx = tid; idx < 8 * 128; idx += 384)
        r_s[(idx >> 7) * HST + (idx & 127)] =
            targets[(size_t)((b0 + (idx >> 7)) * Tk) * 128 + (idx & 127)];
    float* lw = w_s;
    for (int idx = tid; idx < 128 * 256; idx += 384) {
        int o = idx >> 8, k2 = idx & 255;
        lw[k2 * LNS + o] = ln2w[idx];
    }
    __syncthreads();

    if (tid < 128) {
        const int o = tid;
        float acc2[8];
        const float b2 = ln2b[o];
        #pragma unroll
        for (int i = 0; i < 8; i++) acc2[i] = b2;
        #pragma unroll 2
        for (int k = 0; k < 128; k++) {
            float wh = lw[k * LNS + o];
            float wt = lw[(128 + k) * LNS + o];
            int hk = HSWZ(k);
            #pragma unroll
            for (int i = 0; i < 8; i++)
                acc2[i] += h_s[i * HST + hk] * wh + r_s[i * HST + k] * wt;
        }
        #pragma unroll
        for (int i = 0; i < 8; i++)
            out[(size_t)(b0 + i) * 128 + o] = acc2[i];
    }
}

// ---------------------------------------------------------------------------
extern "C" void kernel_launch(void* const* d_in, const int* in_sizes, int n_in,
                              void* d_out, int out_size)
{
    const float* targets = (const float*)d_in[0];
    const float* history = (const float*)d_in[1];
    const float* Ww  = (const float*)d_in[2];
    const float* Wb  = (const float*)d_in[3];
    const float* xuw = (const float*)d_in[4];
    const float* xub = (const float*)d_in[5];
    const float* huw = (const float*)d_in[6];
    const float* hub = (const float*)d_in[7];
    const float* xrw = (const float*)d_in[8];
    const float* xrb = (const float*)d_in[9];
    const float* hrw = (const float*)d_in[10];
    const float* hrb = (const float*)d_in[11];
    const float* xgw = (const float*)d_in[12];
    const float* xgb = (const float*)d_in[13];
    const float* hgw = (const float*)d_in[14];
    const float* hgb = (const float*)d_in[15];
    const float* ln2w = (const float*)d_in[16];
    const float* ln2b = (const float*)d_in[17];
    float* out = (float*)d_out;

    const size_t smC = (size_t)(3 * 128 * WST + 5 * 8 * HST) * sizeof(float);

    cudaFuncSetAttribute(proj_mma_kernel, cudaFuncAttributeMaxDynamicSharedMemorySize, SM_TOT);
    cudaFuncSetAttribute(scan_kernel, cudaFuncAttributeMaxDynamicSharedMemorySize, (int)smC);

    proj_mma_kernel<<<NSL2 * 4, 256, SM_TOT>>>(targets, history, Ww, Wb,
                                               xuw, xub, xrw, xrb, xgw, xgb);
    softmax_kernel<<<Bk, 256>>>();
    scan_kernel<<<Bk / 8, 384, smC>>>(targets, huw, hub, hrw, hrb, hgw, hgb,
                                      ln2w, ln2b, out);
}